// round 14
// baseline (speedup 1.0000x reference)
#include <cuda_runtime.h>
#include <cuda_fp16.h>
#include <cstdint>

// ---------------------------------------------------------------------------
// FCOS head, fp16 mma.sync (m16n8k16, fp32 accum). Level-batched, 4-deep
// cp.async ring. Two streams (cls/reg). R13: gn_coef folded into the tower
// gemm (last-CTA ticket computes GN coefficients); prologue split across
// streams.
// ---------------------------------------------------------------------------

#define TP 20267
#define TOTE 10376704
#define PAD 20
#define NTILES 319
#define STAGE_BYTES 20480
#define DYN_SMEM (4 * STAGE_BYTES)
#define WTN 2359296            // 4*9*256*256

__device__ __half g_xh[TOTE];
__device__ __half g_actA[TOTE];   // cls ping
__device__ __half g_actB[TOTE];   // cls pong
__device__ __half g_actC[TOTE];   // reg ping
__device__ __half g_actD[TOTE];   // reg pong
__device__ float  g_y[TOTE];      // cls conv out
__device__ float  g_y2[TOTE];     // reg conv out
__device__ float  g_gnsum[4 * 640];
__device__ float  g_gnsq[4 * 640];
__device__ float  g_scale[2 * 2560];
__device__ float  g_shift[2 * 2560];
__device__ float  g_regb[26];
__device__ int    g_done[8];
__device__ __half g_wt_cls[WTN];                 // [s][tap][oc][ic]
__device__ __half g_wt_reg[WTN];
__device__ __half g_wtc_out[9 * 128 * 256];      // [tap][ocpad][ic]
__device__ __half g_wtr_out[9 * 128 * 256];

__constant__ int c_Hs[5] = {100, 50, 25, 13, 7};
__constant__ int c_Ws[5] = {152, 76, 38, 19, 10};
__constant__ int c_HWs[5] = {15200, 3800, 950, 247, 70};
__constant__ int c_Ps[5] = {30400, 7600, 1900, 494, 140};
__constant__ int c_tb[5] = {0, 238, 298, 313, 317};
__constant__ int c_ao[5] = {0, 7782400, 9728000, 10214400, 10340864};
__constant__ int c_lb[5] = {0, 15200, 19000, 19950, 20197};

__constant__ long long c_base[26] = {
    3242720LL, 3242720LL, 3242720LL, 3242720LL,
    3404856LL,
    3445390LL, 3445390LL, 3445390LL,
    3566992LL,
    3607526LL, 3607526LL, 3607526LL, 3607526LL, 3607526LL, 3607526LL,
    3607526LL, 3607526LL, 3607526LL, 3607526LL, 3607526LL, 3607526LL,
    3607526LL, 3607526LL, 3607526LL, 3607526LL,
    4256070LL};
__constant__ int c_ctot[26] = {4, 4, 4, 4, 1, 3, 3, 3, 1,
                               16, 16, 16, 16, 16, 16, 16, 16,
                               16, 16, 16, 16, 16, 16, 16, 16, 1};
__constant__ int c_ch[26] = {0, 1, 2, 3, 0, 0, 1, 2, 0,
                             0, 1, 2, 3, 4, 5, 6, 7,
                             8, 9, 10, 11, 12, 13, 14, 15, 0};
__constant__ int c_relu[26] = {1, 1, 1, 1, 0, 0, 0, 0, 0,
                               0, 0, 0, 0, 0, 0, 0, 0,
                               0, 0, 0, 0, 0, 0, 0, 0, 0};

__device__ __forceinline__ void cpa16p(uint32_t d, const void* s, int sz) {
    asm volatile("cp.async.cg.shared.global [%0], [%1], 16, %2;" ::"r"(d), "l"(s), "r"(sz));
}
#define LDSM4(r0, r1, r2, r3, a)                                           \
    asm volatile("ldmatrix.sync.aligned.m8n8.x4.shared.b16 {%0,%1,%2,%3}, [%4];" \
                 : "=r"(r0), "=r"(r1), "=r"(r2), "=r"(r3) : "r"(a))

// ---------------------------------------------------------------------------
// NCHW fp32 -> NHWC half, all levels in one launch. grid (475, 8, 10)
// ---------------------------------------------------------------------------
__global__ void to_nhwc_half(const float* __restrict__ f0, const float* __restrict__ f1,
                             const float* __restrict__ f2, const float* __restrict__ f3,
                             const float* __restrict__ f4, __half* __restrict__ xh) {
    __shared__ float t[32][33];
    int z = blockIdx.z;
    int lvl = z >> 1, n = z & 1;
    int HW = c_HWs[lvl];
    int p0 = blockIdx.x * 32;
    if (p0 >= HW) return;
    const float* src = lvl == 0 ? f0 : lvl == 1 ? f1 : lvl == 2 ? f2 : lvl == 3 ? f3 : f4;
    __half* dst = xh + c_ao[lvl];
    int c0 = blockIdx.y * 32;
    int tx = threadIdx.x, ty = threadIdx.y;
    int p = p0 + tx;
    if (p < HW) t[ty][tx] = src[((size_t)(n * 256 + c0 + ty)) * HW + p];
    __syncthreads();
    int p2 = p0 + ty, c2 = c0 + tx;
    if (p2 < HW) dst[((size_t)(n * HW + p2)) * 256 + c2] = __float2half_rn(t[tx][ty]);
}

// ---------------------------------------------------------------------------
// Per-path weight pack (towers): w[s][oc][ic][tap] -> [s][tap][oc][ic] half
// ---------------------------------------------------------------------------
__global__ void pack_w_path(const float* __restrict__ w, __half* __restrict__ d) {
    int i = blockIdx.x * blockDim.x + threadIdx.x;
    if (i >= WTN) return;
    int ic = i & 255;
    int oc = (i >> 8) & 255;
    int tap = (i >> 16) % 9;
    int s = i / 589824;
    d[i] = __float2half_rn(w[(((size_t)(s * 256 + oc) * 256 + ic) * 9) + tap]);
}

// cls head + stat/counter zeroing
__global__ void pack_small_cls(const float* __restrict__ cls_out_w) {
    int idx = blockIdx.x * blockDim.x + threadIdx.x;
    const int HN = 9 * 128 * 256;
    if (idx < HN) {
        int ic = idx & 255;
        int oc = (idx >> 8) & 127;
        int tap = idx >> 15;
        float v = (oc < 80) ? cls_out_w[((size_t)oc * 256 + ic) * 9 + tap] : 0.f;
        g_wtc_out[idx] = __float2half_rn(v);
    } else if (idx < HN + 2560) {
        g_gnsum[idx - HN] = 0.f;
    } else if (idx < HN + 5120) {
        g_gnsq[idx - HN - 2560] = 0.f;
    } else if (idx < HN + 5120 + 8) {
        g_done[idx - HN - 5120] = 0;
    }
}

// reg head + reg bias
__global__ void pack_small_reg(
    const float* __restrict__ bbox_w, const float* __restrict__ bbox_b,
    const float* __restrict__ ctr_w,  const float* __restrict__ ctr_b,
    const float* __restrict__ dim_w,  const float* __restrict__ dim_b,
    const float* __restrict__ ori_w,  const float* __restrict__ ori_b,
    const float* __restrict__ kp_w,   const float* __restrict__ kp_b,
    const float* __restrict__ depth_w,const float* __restrict__ depth_b) {
    int idx = blockIdx.x * blockDim.x + threadIdx.x;
    const int HN = 9 * 128 * 256;
    if (idx < HN) {
        int ic = idx & 255;
        int oc = (idx >> 8) & 127;
        int tap = idx >> 15;
        float v = 0.f;
        if (oc < 26) {
            const float* src;
            if (oc < 4)       src = bbox_w + oc * 2304;
            else if (oc == 4) src = ctr_w;
            else if (oc < 8)  src = dim_w + (oc - 5) * 2304;
            else if (oc == 8) src = ori_w;
            else if (oc < 25) src = kp_w + (oc - 9) * 2304;
            else              src = depth_w;
            v = src[ic * 9 + tap];
        }
        g_wtr_out[idx] = __float2half_rn(v);
    } else if (idx < HN + 26) {
        int oc = idx - HN;
        float b;
        if (oc < 4)       b = bbox_b[oc];
        else if (oc == 4) b = ctr_b[0];
        else if (oc < 8)  b = dim_b[oc - 5];
        else if (oc == 8) b = ori_b[0];
        else if (oc < 25) b = kp_b[oc - 9];
        else              b = depth_b[0];
        g_regb[oc] = b;
    }
}

// ---------------------------------------------------------------------------
// Per-path fp16 implicit-GEMM conv. M=128 pos x N=128 oc, 8 warps
// (warp tile 64x32). kind 0: tower, grid (NTILES,2); kind 1: head (NTILES,1).
// Tower epilogue emits GN stats; the last CTA computes the GN coef tables.
// ---------------------------------------------------------------------------
__global__ __launch_bounds__(256, 2) void gemm16(
    const __half* __restrict__ xg, const __half* __restrict__ wt,
    const float* __restrict__ bias, float* __restrict__ outp,
    float* __restrict__ gsum, float* __restrict__ gsq,
    const float* __restrict__ gam, const float* __restrict__ bet,
    float* __restrict__ scl, float* __restrict__ shf, int* __restrict__ done,
    int NST, int kind, int path) {
    extern __shared__ __align__(16) uint32_t dynsm[];
    __shared__ int syy[128], sxx[128], sn[128];
    __shared__ int sticket;

    int tid = threadIdx.x;
    int bx = blockIdx.x, by = blockIdx.y;
    int lvl = (bx >= c_tb[1]) + (bx >= c_tb[2]) + (bx >= c_tb[3]) + (bx >= c_tb[4]);
    int H = c_Hs[lvl], W = c_Ws[lvl], HW = c_HWs[lvl], P = c_Ps[lvl];
    int p0 = (bx - c_tb[lvl]) * 128;

    int oc0, OC;
    if (kind == 0) { oc0 = by * 128; OC = 256; }
    else           { oc0 = 0; OC = path ? 26 : 80; }
    const __half* x = xg + c_ao[lvl];

    if (tid < 128) {
        int p = p0 + tid;
        if (p < P) {
            int n = p >= HW ? 1 : 0;
            int rr = p - n * HW;
            int yy = rr / W;
            syy[tid] = yy;
            sxx[tid] = rr - yy * W;
            sn[tid] = n;
        } else {
            syy[tid] = -100000;
            sxx[tid] = -100000;
            sn[tid] = 0;
        }
    }
    __syncthreads();

    int warp = tid >> 5, lane = tid & 31, g = lane >> 2, t4 = lane & 3;
    int mwarp = (warp >> 2) * 64, nwarp = (warp & 3) * 32;

    float acc[4][4][4];
#pragma unroll
    for (int i = 0; i < 4; i++)
#pragma unroll
        for (int j = 0; j < 4; j++)
#pragma unroll
            for (int q = 0; q < 4; q++) acc[i][j][q] = 0.f;

    int m0 = tid >> 2, cw0 = tid & 3;
    uint32_t smbase = (uint32_t)__cvta_generic_to_shared(dynsm);

    int laneA_row = lane & 15;
    int colA = (lane >> 4) * 4;
    int laneB_row = ((lane >> 4) << 3) + (lane & 7);
    int colB = ((lane >> 3) & 1) * 4;
    uint32_t aAoff = ((mwarp + laneA_row) * PAD + colA) * 4;
    uint32_t aBoff = 10240 + ((nwarp + laneB_row) * PAD + colB) * 4;

    auto load_chunk = [&](int c, int slot) {
        int tap = c >> 3;
        int icc = (c & 7) << 5;
        int ty = tap / 3;
        int dy = ty - 1, dx = tap - ty * 3 - 1;
        uint32_t base = smbase + slot * STAGE_BYTES;
#pragma unroll
        for (int j = 0; j < 2; j++) {
            int m = m0 + j * 64;
            int gy = syy[m] + dy, gx = sxx[m] + dx;
            bool v = ((unsigned)gy < (unsigned)H) && ((unsigned)gx < (unsigned)W);
            const __half* src =
                x + ((size_t)(sn[m] * HW + gy * W + gx) * 256 + icc + cw0 * 8);
            cpa16p(base + (m * PAD + cw0 * 4) * 4, v ? src : (const __half*)x,
                   v ? 16 : 0);
        }
        const __half* wbase =
            kind ? wt + ((size_t)(tap * 128)) * 256
                 : wt + ((size_t)(tap * 256 + oc0)) * 256;
#pragma unroll
        for (int j = 0; j < 2; j++) {
            int ocr = m0 + j * 64;
            cpa16p(base + 10240 + (ocr * PAD + cw0 * 4) * 4,
                   wbase + (size_t)ocr * 256 + icc + cw0 * 8, 16);
        }
        asm volatile("cp.async.commit_group;");
    };

    load_chunk(0, 0);
    load_chunk(1, 1);
    load_chunk(2, 2);

    for (int s = 0; s < NST; s++) {
        int slot = s & 3;
        if (s + 2 < NST) {
            asm volatile("cp.async.wait_group 2;");
        } else if (s + 1 < NST) {
            asm volatile("cp.async.wait_group 1;");
        } else {
            asm volatile("cp.async.wait_group 0;");
        }
        __syncthreads();
        if (s + 3 < NST) load_chunk(s + 3, (s + 3) & 3);

        uint32_t sb = smbase + slot * STAGE_BYTES;
        uint32_t aA = sb + aAoff;
        uint32_t aB = sb + aBoff;
#pragma unroll
        for (int kb = 0; kb < 2; kb++) {
            uint32_t kwb = kb * 8 * 4;
            uint32_t A[4][4], Bv[2][4];
#pragma unroll
            for (int mt = 0; mt < 4; mt++)
                LDSM4(A[mt][0], A[mt][1], A[mt][2], A[mt][3],
                      aA + mt * (16 * PAD * 4) + kwb);
#pragma unroll
            for (int ntp = 0; ntp < 2; ntp++)
                LDSM4(Bv[ntp][0], Bv[ntp][1], Bv[ntp][2], Bv[ntp][3],
                      aB + ntp * (16 * PAD * 4) + kwb);
#pragma unroll
            for (int mt = 0; mt < 4; mt++)
#pragma unroll
                for (int nt = 0; nt < 4; nt++) {
                    int ntp = nt >> 1, j = nt & 1;
                    asm volatile(
                        "mma.sync.aligned.m16n8k16.row.col.f32.f16.f16.f32 "
                        "{%0,%1,%2,%3}, {%4,%5,%6,%7}, {%8,%9}, {%0,%1,%2,%3};"
                        : "+f"(acc[mt][nt][0]), "+f"(acc[mt][nt][1]),
                          "+f"(acc[mt][nt][2]), "+f"(acc[mt][nt][3])
                        : "r"(A[mt][0]), "r"(A[mt][1]), "r"(A[mt][2]), "r"(A[mt][3]),
                          "r"(Bv[ntp][j * 2]), "r"(Bv[ntp][j * 2 + 1]));
                }
        }
    }

    // epilogue
#pragma unroll
    for (int nt = 0; nt < 4; nt++) {
        int oc = oc0 + nwarp + nt * 8 + 2 * t4;
        float s0 = 0.f, q0 = 0.f, s1 = 0.f, q1 = 0.f;
#pragma unroll
        for (int mt = 0; mt < 4; mt++) {
#pragma unroll
            for (int hf = 0; hf < 2; hf++) {
                int r = mwarp + mt * 16 + g + hf * 8;
                if (p0 + r >= P) continue;
                float v0 = acc[mt][nt][hf * 2];
                float v1 = acc[mt][nt][hf * 2 + 1];
                if (kind == 0) {
                    v0 += __ldg(&bias[oc]);
                    v1 += __ldg(&bias[oc + 1]);
                    size_t ob = (size_t)c_ao[lvl] + (size_t)(p0 + r) * 256 + oc;
                    float2 st = {v0, v1};
                    *(float2*)&outp[ob] = st;
                    if (sn[r]) { s1 += v0 + v1; q1 += v0 * v0 + v1 * v1; }
                    else       { s0 += v0 + v1; q0 += v0 * v0 + v1 * v1; }
                } else if (oc < OC) {
                    long long unit =
                        (long long)sn[r] * TP + c_lb[lvl] + syy[r] * W + sxx[r];
                    v0 += __ldg(&bias[oc]);
                    v1 += __ldg(&bias[oc + 1]);
                    if (path == 0) {
                        outp[unit * 80 + oc] = v0;
                        outp[unit * 80 + oc + 1] = v1;
                    } else {
                        bool two = (oc + 1) < OC;
                        if (c_relu[oc]) v0 = fmaxf(v0, 0.f);
                        outp[c_base[oc] + unit * c_ctot[oc] + c_ch[oc]] = v0;
                        if (two) {
                            if (c_relu[oc + 1]) v1 = fmaxf(v1, 0.f);
                            outp[c_base[oc + 1] + unit * c_ctot[oc + 1] +
                                 c_ch[oc + 1]] = v1;
                        }
                    }
                }
            }
        }
        if (kind == 0) {
#pragma unroll
            for (int o = 16; o > 0; o >>= 1) {
                s0 += __shfl_xor_sync(0xffffffffu, s0, o);
                q0 += __shfl_xor_sync(0xffffffffu, q0, o);
                s1 += __shfl_xor_sync(0xffffffffu, s1, o);
                q1 += __shfl_xor_sync(0xffffffffu, q1, o);
            }
            if (lane == 0) {
                int gb = lvl * 64 + ((oc0 + nwarp + nt * 8) >> 3);
                atomicAdd(&gsum[gb], s0);
                atomicAdd(&gsq[gb], q0);
                if (s1 != 0.f || q1 != 0.f) {
                    atomicAdd(&gsum[gb + 32], s1);
                    atomicAdd(&gsq[gb + 32], q1);
                }
            }
        }
    }

    // last CTA computes GN coefficient tables for this (stage, path)
    if (kind == 0) {
        __threadfence();
        if (tid == 0) sticket = atomicAdd(done, 1);
        __syncthreads();
        if (sticket == (int)(gridDim.x * gridDim.y) - 1) {
            for (int ng = tid; ng < 320; ng += 256) {
                int l = ng >> 6;
                int r = ng & 63;
                int n = r >> 5, gr = r & 31;
                float M = 8.f * c_HWs[l];
                float mu = __ldcg(&gsum[ng]) / M;
                float iv = rsqrtf(__ldcg(&gsq[ng]) / M - mu * mu + 1e-5f);
                int base = l * 512 + n * 256 + gr * 8;
#pragma unroll
                for (int j = 0; j < 8; j++) {
                    int ch = gr * 8 + j;
                    float sv = iv * gam[ch];
                    scl[base + j] = sv;
                    shf[base + j] = bet[ch] - mu * sv;
                }
            }
            if (tid == 0) *done = 0;   // reset for next replay
        }
    }
}

// ---------------------------------------------------------------------------
// GroupNorm apply (per path): v*scale + shift, relu, to half.
// ---------------------------------------------------------------------------
__global__ void gn_apply(const float* __restrict__ y, __half* __restrict__ act,
                         const float* __restrict__ scl, const float* __restrict__ shf) {
    int idx = blockIdx.x * blockDim.x + threadIdx.x;
    if (idx >= TOTE / 4) return;
    int e = idx * 4;
    int l = (e >= c_ao[1]) + (e >= c_ao[2]) + (e >= c_ao[3]) + (e >= c_ao[4]);
    int c = e & 255;
    int pl = (e - c_ao[l]) >> 8;
    int n = pl >= c_HWs[l] ? 1 : 0;
    int cb = l * 512 + n * 256 + c;
    float4 sc = *(const float4*)&scl[cb];
    float4 sh = *(const float4*)&shf[cb];
    float4 v = *(const float4*)&y[e];
    __half2 h0 = __floats2half2_rn(fmaxf(v.x * sc.x + sh.x, 0.f),
                                   fmaxf(v.y * sc.y + sh.y, 0.f));
    __half2 h1 = __floats2half2_rn(fmaxf(v.z * sc.z + sh.z, 0.f),
                                   fmaxf(v.w * sc.w + sh.w, 0.f));
    uint2 st = {*(uint32_t*)&h0, *(uint32_t*)&h1};
    *(uint2*)&act[e] = st;
}

// ---------------------------------------------------------------------------
// Host orchestration: cls chain on default stream, reg chain on side stream.
// ---------------------------------------------------------------------------
extern "C" void kernel_launch(void* const* d_in, const int* in_sizes, int n_in,
                              void* d_out, int out_size) {
    const float* feats[5];
    for (int i = 0; i < 5; i++) feats[i] = (const float*)d_in[i];
    const float* cls_conv_w = (const float*)d_in[5];
    const float* cls_conv_b = (const float*)d_in[6];
    const float* cls_gn_w = (const float*)d_in[7];
    const float* cls_gn_b = (const float*)d_in[8];
    const float* cls_out_w = (const float*)d_in[9];
    const float* cls_out_b = (const float*)d_in[10];
    const float* reg_conv_w = (const float*)d_in[11];
    const float* reg_conv_b = (const float*)d_in[12];
    const float* reg_gn_w = (const float*)d_in[13];
    const float* reg_gn_b = (const float*)d_in[14];
    float* out = (float*)d_out;

    __half *xh, *actA, *actB, *actC, *actD, *wtc, *wtr, *wtco, *wtro;
    float *ybuf, *ybuf2, *regb, *gsum, *gsq, *scl, *shf;
    int* done;
    cudaGetSymbolAddress((void**)&xh, g_xh);
    cudaGetSymbolAddress((void**)&actA, g_actA);
    cudaGetSymbolAddress((void**)&actB, g_actB);
    cudaGetSymbolAddress((void**)&actC, g_actC);
    cudaGetSymbolAddress((void**)&actD, g_actD);
    cudaGetSymbolAddress((void**)&ybuf, g_y);
    cudaGetSymbolAddress((void**)&ybuf2, g_y2);
    cudaGetSymbolAddress((void**)&regb, g_regb);
    cudaGetSymbolAddress((void**)&wtc, g_wt_cls);
    cudaGetSymbolAddress((void**)&wtr, g_wt_reg);
    cudaGetSymbolAddress((void**)&wtco, g_wtc_out);
    cudaGetSymbolAddress((void**)&wtro, g_wtr_out);
    cudaGetSymbolAddress((void**)&gsum, g_gnsum);
    cudaGetSymbolAddress((void**)&gsq, g_gnsq);
    cudaGetSymbolAddress((void**)&scl, g_scale);
    cudaGetSymbolAddress((void**)&shf, g_shift);
    cudaGetSymbolAddress((void**)&done, g_done);

    cudaFuncSetAttribute(gemm16, cudaFuncAttributeMaxDynamicSharedMemorySize,
                         DYN_SMEM);

    static cudaStream_t s1 = nullptr;
    static cudaEvent_t eF = nullptr, eJ = nullptr;
    if (!s1) {
        cudaStreamCreateWithFlags(&s1, cudaStreamNonBlocking);
        cudaEventCreateWithFlags(&eF, cudaEventDisableTiming);
        cudaEventCreateWithFlags(&eJ, cudaEventDisableTiming);
    }

    // prologue: stream0 = cls pack + zeroing + transpose; s1 = reg packs
    pack_w_path<<<(WTN + 255) / 256, 256>>>(cls_conv_w, wtc);
    {
        int tot = 9 * 128 * 256 + 5120 + 8;
        pack_small_cls<<<(tot + 255) / 256, 256>>>(cls_out_w);
    }
    to_nhwc_half<<<dim3(475, 8, 10), dim3(32, 32)>>>(feats[0], feats[1], feats[2],
                                                     feats[3], feats[4], xh);
    cudaEventRecord(eF, 0);

    pack_w_path<<<(WTN + 255) / 256, 256, 0, s1>>>(reg_conv_w, wtr);
    {
        int tot = 9 * 128 * 256 + 26;
        pack_small_reg<<<(tot + 255) / 256, 256, 0, s1>>>(
            (const float*)d_in[15], (const float*)d_in[16],
            (const float*)d_in[17], (const float*)d_in[18],
            (const float*)d_in[19], (const float*)d_in[20],
            (const float*)d_in[21], (const float*)d_in[22],
            (const float*)d_in[23], (const float*)d_in[24],
            (const float*)d_in[25], (const float*)d_in[26]);
    }
    cudaStreamWaitEvent(s1, eF, 0);   // xh + stat zeroing ready

    int gApplyX = (TOTE / 4 + 255) / 256;

    // --- cls chain (default stream) ---
    {
        const __half* cur = xh;
        __half* cd[4] = {actA, actB, actA, actB};
        for (int s = 0; s < 4; s++) {
            gemm16<<<dim3(NTILES, 2), 256, DYN_SMEM>>>(
                cur, wtc + (size_t)s * 589824, cls_conv_b + s * 256, ybuf,
                gsum + s * 640, gsq + s * 640,
                cls_gn_w + s * 256, cls_gn_b + s * 256, scl, shf,
                done + s * 2, 72, 0, 0);
            gn_apply<<<gApplyX, 256>>>(ybuf, cd[s], scl, shf);
            cur = cd[s];
        }
        gemm16<<<dim3(NTILES, 1), 256, DYN_SMEM>>>(
            actB, wtco, cls_out_b, out, nullptr, nullptr, nullptr, nullptr,
            nullptr, nullptr, nullptr, 72, 1, 0);
    }

    // --- reg chain (s1) ---
    {
        const __half* cur = xh;
        __half* rd[4] = {actC, actD, actC, actD};
        for (int s = 0; s < 4; s++) {
            gemm16<<<dim3(NTILES, 2), 256, DYN_SMEM, s1>>>(
                cur, wtr + (size_t)s * 589824, reg_conv_b + s * 256, ybuf2,
                gsum + s * 640 + 320, gsq + s * 640 + 320,
                reg_gn_w + s * 256, reg_gn_b + s * 256, scl + 2560, shf + 2560,
                done + s * 2 + 1, 72, 0, 1);
            gn_apply<<<gApplyX, 256, 0, s1>>>(ybuf2, rd[s], scl + 2560, shf + 2560);
            cur = rd[s];
        }
        gemm16<<<dim3(NTILES, 1), 256, DYN_SMEM, s1>>>(
            actD, wtro, regb, out, nullptr, nullptr, nullptr, nullptr,
            nullptr, nullptr, nullptr, 72, 1, 1);
    }

    // join
    cudaEventRecord(eJ, s1);
    cudaStreamWaitEvent(0, eJ, 0);

    (void)in_sizes; (void)n_in; (void)out_size;
}

// round 15
// speedup vs baseline: 1.0525x; 1.0525x over previous
#include <cuda_runtime.h>
#include <cuda_fp16.h>
#include <cstdint>

// ---------------------------------------------------------------------------
// FCOS head, fp16 mma.sync (m16n8k16, fp32 accum). Level-batched, 4-deep
// cp.async ring. Two streams (cls/reg chains). R14 = R12 core (separate
// gn_coef kernel, clean gemm) + prologue split across the two streams.
// ---------------------------------------------------------------------------

#define TP 20267
#define TOTE 10376704
#define PAD 20
#define NTILES 319
#define STAGE_BYTES 20480
#define DYN_SMEM (4 * STAGE_BYTES)
#define WTN 2359296            // 4*9*256*256

__device__ __half g_xh[TOTE];
__device__ __half g_actA[TOTE];   // cls ping
__device__ __half g_actB[TOTE];   // cls pong
__device__ __half g_actC[TOTE];   // reg ping
__device__ __half g_actD[TOTE];   // reg pong
__device__ float  g_y[TOTE];      // cls conv out
__device__ float  g_y2[TOTE];     // reg conv out
__device__ float  g_gnsum[4 * 640];
__device__ float  g_gnsq[4 * 640];
__device__ float  g_scale[2 * 2560];
__device__ float  g_shift[2 * 2560];
__device__ float  g_regb[26];
__device__ __half g_wt_cls[WTN];                 // [s][tap][oc][ic]
__device__ __half g_wt_reg[WTN];
__device__ __half g_wtc_out[9 * 128 * 256];      // [tap][ocpad][ic]
__device__ __half g_wtr_out[9 * 128 * 256];

__constant__ int c_Hs[5] = {100, 50, 25, 13, 7};
__constant__ int c_Ws[5] = {152, 76, 38, 19, 10};
__constant__ int c_HWs[5] = {15200, 3800, 950, 247, 70};
__constant__ int c_Ps[5] = {30400, 7600, 1900, 494, 140};
__constant__ int c_tb[5] = {0, 238, 298, 313, 317};
__constant__ int c_ao[5] = {0, 7782400, 9728000, 10214400, 10340864};
__constant__ int c_lb[5] = {0, 15200, 19000, 19950, 20197};

__constant__ long long c_base[26] = {
    3242720LL, 3242720LL, 3242720LL, 3242720LL,
    3404856LL,
    3445390LL, 3445390LL, 3445390LL,
    3566992LL,
    3607526LL, 3607526LL, 3607526LL, 3607526LL, 3607526LL, 3607526LL,
    3607526LL, 3607526LL, 3607526LL, 3607526LL, 3607526LL, 3607526LL,
    3607526LL, 3607526LL, 3607526LL, 3607526LL,
    4256070LL};
__constant__ int c_ctot[26] = {4, 4, 4, 4, 1, 3, 3, 3, 1,
                               16, 16, 16, 16, 16, 16, 16, 16,
                               16, 16, 16, 16, 16, 16, 16, 16, 1};
__constant__ int c_ch[26] = {0, 1, 2, 3, 0, 0, 1, 2, 0,
                             0, 1, 2, 3, 4, 5, 6, 7,
                             8, 9, 10, 11, 12, 13, 14, 15, 0};
__constant__ int c_relu[26] = {1, 1, 1, 1, 0, 0, 0, 0, 0,
                               0, 0, 0, 0, 0, 0, 0, 0,
                               0, 0, 0, 0, 0, 0, 0, 0, 0};

__device__ __forceinline__ void cpa16p(uint32_t d, const void* s, int sz) {
    asm volatile("cp.async.cg.shared.global [%0], [%1], 16, %2;" ::"r"(d), "l"(s), "r"(sz));
}
#define LDSM4(r0, r1, r2, r3, a)                                           \
    asm volatile("ldmatrix.sync.aligned.m8n8.x4.shared.b16 {%0,%1,%2,%3}, [%4];" \
                 : "=r"(r0), "=r"(r1), "=r"(r2), "=r"(r3) : "r"(a))

// ---------------------------------------------------------------------------
// NCHW fp32 -> NHWC half, all levels in one launch. grid (475, 8, 10)
// ---------------------------------------------------------------------------
__global__ void to_nhwc_half(const float* __restrict__ f0, const float* __restrict__ f1,
                             const float* __restrict__ f2, const float* __restrict__ f3,
                             const float* __restrict__ f4, __half* __restrict__ xh) {
    __shared__ float t[32][33];
    int z = blockIdx.z;
    int lvl = z >> 1, n = z & 1;
    int HW = c_HWs[lvl];
    int p0 = blockIdx.x * 32;
    if (p0 >= HW) return;
    const float* src = lvl == 0 ? f0 : lvl == 1 ? f1 : lvl == 2 ? f2 : lvl == 3 ? f3 : f4;
    __half* dst = xh + c_ao[lvl];
    int c0 = blockIdx.y * 32;
    int tx = threadIdx.x, ty = threadIdx.y;
    int p = p0 + tx;
    if (p < HW) t[ty][tx] = src[((size_t)(n * 256 + c0 + ty)) * HW + p];
    __syncthreads();
    int p2 = p0 + ty, c2 = c0 + tx;
    if (p2 < HW) dst[((size_t)(n * HW + p2)) * 256 + c2] = __float2half_rn(t[tx][ty]);
}

// ---------------------------------------------------------------------------
// Per-path tower weight pack
// ---------------------------------------------------------------------------
__global__ void pack_w_path(const float* __restrict__ w, __half* __restrict__ d) {
    int i = blockIdx.x * blockDim.x + threadIdx.x;
    if (i >= WTN) return;
    int ic = i & 255;
    int oc = (i >> 8) & 255;
    int tap = (i >> 16) % 9;
    int s = i / 589824;
    d[i] = __float2half_rn(w[(((size_t)(s * 256 + oc) * 256 + ic) * 9) + tap]);
}

// cls head + stat zeroing
__global__ void pack_small_cls(const float* __restrict__ cls_out_w) {
    int idx = blockIdx.x * blockDim.x + threadIdx.x;
    const int HN = 9 * 128 * 256;
    if (idx < HN) {
        int ic = idx & 255;
        int oc = (idx >> 8) & 127;
        int tap = idx >> 15;
        float v = (oc < 80) ? cls_out_w[((size_t)oc * 256 + ic) * 9 + tap] : 0.f;
        g_wtc_out[idx] = __float2half_rn(v);
    } else if (idx < HN + 2560) {
        g_gnsum[idx - HN] = 0.f;
    } else if (idx < HN + 5120) {
        g_gnsq[idx - HN - 2560] = 0.f;
    }
}

// reg head + reg bias
__global__ void pack_small_reg(
    const float* __restrict__ bbox_w, const float* __restrict__ bbox_b,
    const float* __restrict__ ctr_w,  const float* __restrict__ ctr_b,
    const float* __restrict__ dim_w,  const float* __restrict__ dim_b,
    const float* __restrict__ ori_w,  const float* __restrict__ ori_b,
    const float* __restrict__ kp_w,   const float* __restrict__ kp_b,
    const float* __restrict__ depth_w,const float* __restrict__ depth_b) {
    int idx = blockIdx.x * blockDim.x + threadIdx.x;
    const int HN = 9 * 128 * 256;
    if (idx < HN) {
        int ic = idx & 255;
        int oc = (idx >> 8) & 127;
        int tap = idx >> 15;
        float v = 0.f;
        if (oc < 26) {
            const float* src;
            if (oc < 4)       src = bbox_w + oc * 2304;
            else if (oc == 4) src = ctr_w;
            else if (oc < 8)  src = dim_w + (oc - 5) * 2304;
            else if (oc == 8) src = ori_w;
            else if (oc < 25) src = kp_w + (oc - 9) * 2304;
            else              src = depth_w;
            v = src[ic * 9 + tap];
        }
        g_wtr_out[idx] = __float2half_rn(v);
    } else if (idx < HN + 26) {
        int oc = idx - HN;
        float b;
        if (oc < 4)       b = bbox_b[oc];
        else if (oc == 4) b = ctr_b[0];
        else if (oc < 8)  b = dim_b[oc - 5];
        else if (oc == 8) b = ori_b[0];
        else if (oc < 25) b = kp_b[oc - 9];
        else              b = depth_b[0];
        g_regb[oc] = b;
    }
}

// ---------------------------------------------------------------------------
// Per-path fp16 implicit-GEMM conv. M=128 pos x N=128 oc, 8 warps
// (warp tile 64x32). kind 0: tower, grid (NTILES,2); kind 1: head (NTILES,1).
// ---------------------------------------------------------------------------
__global__ __launch_bounds__(256, 2) void gemm16(
    const __half* __restrict__ xg, const __half* __restrict__ wt,
    const float* __restrict__ bias, float* __restrict__ outp,
    float* __restrict__ gsum, float* __restrict__ gsq, int NST, int kind,
    int path) {
    extern __shared__ __align__(16) uint32_t dynsm[];
    __shared__ int syy[128], sxx[128], sn[128];

    int tid = threadIdx.x;
    int bx = blockIdx.x, by = blockIdx.y;
    int lvl = (bx >= c_tb[1]) + (bx >= c_tb[2]) + (bx >= c_tb[3]) + (bx >= c_tb[4]);
    int H = c_Hs[lvl], W = c_Ws[lvl], HW = c_HWs[lvl], P = c_Ps[lvl];
    int p0 = (bx - c_tb[lvl]) * 128;

    int oc0, OC;
    if (kind == 0) { oc0 = by * 128; OC = 256; }
    else           { oc0 = 0; OC = path ? 26 : 80; }
    const __half* x = xg + c_ao[lvl];

    if (tid < 128) {
        int p = p0 + tid;
        if (p < P) {
            int n = p >= HW ? 1 : 0;
            int rr = p - n * HW;
            int yy = rr / W;
            syy[tid] = yy;
            sxx[tid] = rr - yy * W;
            sn[tid] = n;
        } else {
            syy[tid] = -100000;
            sxx[tid] = -100000;
            sn[tid] = 0;
        }
    }
    __syncthreads();

    int warp = tid >> 5, lane = tid & 31, g = lane >> 2, t4 = lane & 3;
    int mwarp = (warp >> 2) * 64, nwarp = (warp & 3) * 32;

    float acc[4][4][4];
#pragma unroll
    for (int i = 0; i < 4; i++)
#pragma unroll
        for (int j = 0; j < 4; j++)
#pragma unroll
            for (int q = 0; q < 4; q++) acc[i][j][q] = 0.f;

    int m0 = tid >> 2, cw0 = tid & 3;
    uint32_t smbase = (uint32_t)__cvta_generic_to_shared(dynsm);

    int laneA_row = lane & 15;
    int colA = (lane >> 4) * 4;
    int laneB_row = ((lane >> 4) << 3) + (lane & 7);
    int colB = ((lane >> 3) & 1) * 4;
    uint32_t aAoff = ((mwarp + laneA_row) * PAD + colA) * 4;
    uint32_t aBoff = 10240 + ((nwarp + laneB_row) * PAD + colB) * 4;

    auto load_chunk = [&](int c, int slot) {
        int tap = c >> 3;
        int icc = (c & 7) << 5;
        int ty = tap / 3;
        int dy = ty - 1, dx = tap - ty * 3 - 1;
        uint32_t base = smbase + slot * STAGE_BYTES;
#pragma unroll
        for (int j = 0; j < 2; j++) {
            int m = m0 + j * 64;
            int gy = syy[m] + dy, gx = sxx[m] + dx;
            bool v = ((unsigned)gy < (unsigned)H) && ((unsigned)gx < (unsigned)W);
            const __half* src =
                x + ((size_t)(sn[m] * HW + gy * W + gx) * 256 + icc + cw0 * 8);
            cpa16p(base + (m * PAD + cw0 * 4) * 4, v ? src : (const __half*)x,
                   v ? 16 : 0);
        }
        const __half* wbase =
            kind ? wt + ((size_t)(tap * 128)) * 256
                 : wt + ((size_t)(tap * 256 + oc0)) * 256;
#pragma unroll
        for (int j = 0; j < 2; j++) {
            int ocr = m0 + j * 64;
            cpa16p(base + 10240 + (ocr * PAD + cw0 * 4) * 4,
                   wbase + (size_t)ocr * 256 + icc + cw0 * 8, 16);
        }
        asm volatile("cp.async.commit_group;");
    };

    load_chunk(0, 0);
    load_chunk(1, 1);
    load_chunk(2, 2);

    for (int s = 0; s < NST; s++) {
        int slot = s & 3;
        if (s + 2 < NST) {
            asm volatile("cp.async.wait_group 2;");
        } else if (s + 1 < NST) {
            asm volatile("cp.async.wait_group 1;");
        } else {
            asm volatile("cp.async.wait_group 0;");
        }
        __syncthreads();
        if (s + 3 < NST) load_chunk(s + 3, (s + 3) & 3);

        uint32_t sb = smbase + slot * STAGE_BYTES;
        uint32_t aA = sb + aAoff;
        uint32_t aB = sb + aBoff;
#pragma unroll
        for (int kb = 0; kb < 2; kb++) {
            uint32_t kwb = kb * 8 * 4;
            uint32_t A[4][4], Bv[2][4];
#pragma unroll
            for (int mt = 0; mt < 4; mt++)
                LDSM4(A[mt][0], A[mt][1], A[mt][2], A[mt][3],
                      aA + mt * (16 * PAD * 4) + kwb);
#pragma unroll
            for (int ntp = 0; ntp < 2; ntp++)
                LDSM4(Bv[ntp][0], Bv[ntp][1], Bv[ntp][2], Bv[ntp][3],
                      aB + ntp * (16 * PAD * 4) + kwb);
#pragma unroll
            for (int mt = 0; mt < 4; mt++)
#pragma unroll
                for (int nt = 0; nt < 4; nt++) {
                    int ntp = nt >> 1, j = nt & 1;
                    asm volatile(
                        "mma.sync.aligned.m16n8k16.row.col.f32.f16.f16.f32 "
                        "{%0,%1,%2,%3}, {%4,%5,%6,%7}, {%8,%9}, {%0,%1,%2,%3};"
                        : "+f"(acc[mt][nt][0]), "+f"(acc[mt][nt][1]),
                          "+f"(acc[mt][nt][2]), "+f"(acc[mt][nt][3])
                        : "r"(A[mt][0]), "r"(A[mt][1]), "r"(A[mt][2]), "r"(A[mt][3]),
                          "r"(Bv[ntp][j * 2]), "r"(Bv[ntp][j * 2 + 1]));
                }
        }
    }

    // epilogue
#pragma unroll
    for (int nt = 0; nt < 4; nt++) {
        int oc = oc0 + nwarp + nt * 8 + 2 * t4;
        float s0 = 0.f, q0 = 0.f, s1 = 0.f, q1 = 0.f;
#pragma unroll
        for (int mt = 0; mt < 4; mt++) {
#pragma unroll
            for (int hf = 0; hf < 2; hf++) {
                int r = mwarp + mt * 16 + g + hf * 8;
                if (p0 + r >= P) continue;
                float v0 = acc[mt][nt][hf * 2];
                float v1 = acc[mt][nt][hf * 2 + 1];
                if (kind == 0) {
                    v0 += __ldg(&bias[oc]);
                    v1 += __ldg(&bias[oc + 1]);
                    size_t ob = (size_t)c_ao[lvl] + (size_t)(p0 + r) * 256 + oc;
                    float2 st = {v0, v1};
                    *(float2*)&outp[ob] = st;
                    if (sn[r]) { s1 += v0 + v1; q1 += v0 * v0 + v1 * v1; }
                    else       { s0 += v0 + v1; q0 += v0 * v0 + v1 * v1; }
                } else if (oc < OC) {
                    long long unit =
                        (long long)sn[r] * TP + c_lb[lvl] + syy[r] * W + sxx[r];
                    v0 += __ldg(&bias[oc]);
                    v1 += __ldg(&bias[oc + 1]);
                    if (path == 0) {
                        outp[unit * 80 + oc] = v0;
                        outp[unit * 80 + oc + 1] = v1;
                    } else {
                        bool two = (oc + 1) < OC;
                        if (c_relu[oc]) v0 = fmaxf(v0, 0.f);
                        outp[c_base[oc] + unit * c_ctot[oc] + c_ch[oc]] = v0;
                        if (two) {
                            if (c_relu[oc + 1]) v1 = fmaxf(v1, 0.f);
                            outp[c_base[oc + 1] + unit * c_ctot[oc + 1] +
                                 c_ch[oc + 1]] = v1;
                        }
                    }
                }
            }
        }
        if (kind == 0) {
#pragma unroll
            for (int o = 16; o > 0; o >>= 1) {
                s0 += __shfl_xor_sync(0xffffffffu, s0, o);
                q0 += __shfl_xor_sync(0xffffffffu, q0, o);
                s1 += __shfl_xor_sync(0xffffffffu, s1, o);
                q1 += __shfl_xor_sync(0xffffffffu, q1, o);
            }
            if (lane == 0) {
                int gb = lvl * 64 + ((oc0 + nwarp + nt * 8) >> 3);
                atomicAdd(&gsum[gb], s0);
                atomicAdd(&gsq[gb], q0);
                if (s1 != 0.f || q1 != 0.f) {
                    atomicAdd(&gsum[gb + 32], s1);
                    atomicAdd(&gsq[gb + 32], q1);
                }
            }
        }
    }
}

// ---------------------------------------------------------------------------
// GN coefficients per path: 320 groups -> per-channel scale/shift.
// ---------------------------------------------------------------------------
__global__ void gn_coef(const float* __restrict__ gsum, const float* __restrict__ gsq,
                        const float* __restrict__ gam, const float* __restrict__ bet,
                        float* __restrict__ scl, float* __restrict__ shf) {
    int ng = blockIdx.x * blockDim.x + threadIdx.x;
    if (ng >= 320) return;
    int l = ng >> 6;
    int r = ng & 63;
    int n = r >> 5, gr = r & 31;
    float M = 8.f * c_HWs[l];
    float mu = gsum[ng] / M;
    float iv = rsqrtf(gsq[ng] / M - mu * mu + 1e-5f);
    int base = l * 512 + n * 256 + gr * 8;
#pragma unroll
    for (int j = 0; j < 8; j++) {
        int c = gr * 8 + j;
        float s = iv * gam[c];
        scl[base + j] = s;
        shf[base + j] = bet[c] - mu * s;
    }
}

// ---------------------------------------------------------------------------
// GroupNorm apply (per path): v*scale + shift, relu, to half.
// ---------------------------------------------------------------------------
__global__ void gn_apply(const float* __restrict__ y, __half* __restrict__ act,
                         const float* __restrict__ scl, const float* __restrict__ shf) {
    int idx = blockIdx.x * blockDim.x + threadIdx.x;
    if (idx >= TOTE / 4) return;
    int e = idx * 4;
    int l = (e >= c_ao[1]) + (e >= c_ao[2]) + (e >= c_ao[3]) + (e >= c_ao[4]);
    int c = e & 255;
    int pl = (e - c_ao[l]) >> 8;
    int n = pl >= c_HWs[l] ? 1 : 0;
    int cb = l * 512 + n * 256 + c;
    float4 sc = *(const float4*)&scl[cb];
    float4 sh = *(const float4*)&shf[cb];
    float4 v = *(const float4*)&y[e];
    __half2 h0 = __floats2half2_rn(fmaxf(v.x * sc.x + sh.x, 0.f),
                                   fmaxf(v.y * sc.y + sh.y, 0.f));
    __half2 h1 = __floats2half2_rn(fmaxf(v.z * sc.z + sh.z, 0.f),
                                   fmaxf(v.w * sc.w + sh.w, 0.f));
    uint2 st = {*(uint32_t*)&h0, *(uint32_t*)&h1};
    *(uint2*)&act[e] = st;
}

// ---------------------------------------------------------------------------
// Host orchestration: cls chain on default stream, reg chain on side stream.
// ---------------------------------------------------------------------------
extern "C" void kernel_launch(void* const* d_in, const int* in_sizes, int n_in,
                              void* d_out, int out_size) {
    const float* feats[5];
    for (int i = 0; i < 5; i++) feats[i] = (const float*)d_in[i];
    const float* cls_conv_w = (const float*)d_in[5];
    const float* cls_conv_b = (const float*)d_in[6];
    const float* cls_gn_w = (const float*)d_in[7];
    const float* cls_gn_b = (const float*)d_in[8];
    const float* cls_out_w = (const float*)d_in[9];
    const float* cls_out_b = (const float*)d_in[10];
    const float* reg_conv_w = (const float*)d_in[11];
    const float* reg_conv_b = (const float*)d_in[12];
    const float* reg_gn_w = (const float*)d_in[13];
    const float* reg_gn_b = (const float*)d_in[14];
    float* out = (float*)d_out;

    __half *xh, *actA, *actB, *actC, *actD, *wtc, *wtr, *wtco, *wtro;
    float *ybuf, *ybuf2, *regb, *gsum, *gsq, *scl, *shf;
    cudaGetSymbolAddress((void**)&xh, g_xh);
    cudaGetSymbolAddress((void**)&actA, g_actA);
    cudaGetSymbolAddress((void**)&actB, g_actB);
    cudaGetSymbolAddress((void**)&actC, g_actC);
    cudaGetSymbolAddress((void**)&actD, g_actD);
    cudaGetSymbolAddress((void**)&ybuf, g_y);
    cudaGetSymbolAddress((void**)&ybuf2, g_y2);
    cudaGetSymbolAddress((void**)&regb, g_regb);
    cudaGetSymbolAddress((void**)&wtc, g_wt_cls);
    cudaGetSymbolAddress((void**)&wtr, g_wt_reg);
    cudaGetSymbolAddress((void**)&wtco, g_wtc_out);
    cudaGetSymbolAddress((void**)&wtro, g_wtr_out);
    cudaGetSymbolAddress((void**)&gsum, g_gnsum);
    cudaGetSymbolAddress((void**)&gsq, g_gnsq);
    cudaGetSymbolAddress((void**)&scl, g_scale);
    cudaGetSymbolAddress((void**)&shf, g_shift);

    cudaFuncSetAttribute(gemm16, cudaFuncAttributeMaxDynamicSharedMemorySize,
                         DYN_SMEM);

    static cudaStream_t s1 = nullptr;
    static cudaEvent_t eF = nullptr, eJ = nullptr;
    if (!s1) {
        cudaStreamCreateWithFlags(&s1, cudaStreamNonBlocking);
        cudaEventCreateWithFlags(&eF, cudaEventDisableTiming);
        cudaEventCreateWithFlags(&eJ, cudaEventDisableTiming);
    }

    // prologue: stream0 = cls packs + stat zeroing + transpose; s1 = reg packs
    pack_w_path<<<(WTN + 255) / 256, 256>>>(cls_conv_w, wtc);
    {
        int tot = 9 * 128 * 256 + 5120;
        pack_small_cls<<<(tot + 255) / 256, 256>>>(cls_out_w);
    }
    to_nhwc_half<<<dim3(475, 8, 10), dim3(32, 32)>>>(feats[0], feats[1], feats[2],
                                                     feats[3], feats[4], xh);
    cudaEventRecord(eF, 0);

    pack_w_path<<<(WTN + 255) / 256, 256, 0, s1>>>(reg_conv_w, wtr);
    {
        int tot = 9 * 128 * 256 + 26;
        pack_small_reg<<<(tot + 255) / 256, 256, 0, s1>>>(
            (const float*)d_in[15], (const float*)d_in[16],
            (const float*)d_in[17], (const float*)d_in[18],
            (const float*)d_in[19], (const float*)d_in[20],
            (const float*)d_in[21], (const float*)d_in[22],
            (const float*)d_in[23], (const float*)d_in[24],
            (const float*)d_in[25], (const float*)d_in[26]);
    }
    cudaStreamWaitEvent(s1, eF, 0);   // xh + stat zeroing ready

    int gApplyX = (TOTE / 4 + 255) / 256;

    // --- cls chain (default stream) ---
    {
        const __half* cur = xh;
        __half* cd[4] = {actA, actB, actA, actB};
        for (int s = 0; s < 4; s++) {
            gemm16<<<dim3(NTILES, 2), 256, DYN_SMEM>>>(
                cur, wtc + (size_t)s * 589824, cls_conv_b + s * 256, ybuf,
                gsum + s * 640, gsq + s * 640, 72, 0, 0);
            gn_coef<<<2, 160>>>(gsum + s * 640, gsq + s * 640,
                                cls_gn_w + s * 256, cls_gn_b + s * 256, scl, shf);
            gn_apply<<<gApplyX, 256>>>(ybuf, cd[s], scl, shf);
            cur = cd[s];
        }
        gemm16<<<dim3(NTILES, 1), 256, DYN_SMEM>>>(actB, wtco, cls_out_b, out,
                                                   nullptr, nullptr, 72, 1, 0);
    }

    // --- reg chain (s1) ---
    {
        const __half* cur = xh;
        __half* rd[4] = {actC, actD, actC, actD};
        for (int s = 0; s < 4; s++) {
            gemm16<<<dim3(NTILES, 2), 256, DYN_SMEM, s1>>>(
                cur, wtr + (size_t)s * 589824, reg_conv_b + s * 256, ybuf2,
                gsum + s * 640 + 320, gsq + s * 640 + 320, 72, 0, 1);
            gn_coef<<<2, 160, 0, s1>>>(gsum + s * 640 + 320, gsq + s * 640 + 320,
                                       reg_gn_w + s * 256, reg_gn_b + s * 256,
                                       scl + 2560, shf + 2560);
            gn_apply<<<gApplyX, 256, 0, s1>>>(ybuf2, rd[s], scl + 2560, shf + 2560);
            cur = rd[s];
        }
        gemm16<<<dim3(NTILES, 1), 256, DYN_SMEM, s1>>>(actD, wtro, regb, out,
                                                       nullptr, nullptr, 72, 1, 1);
    }

    // join
    cudaEventRecord(eJ, s1);
    cudaStreamWaitEvent(0, eJ, 0);

    (void)in_sizes; (void)n_in; (void)out_size;
}

// round 16
// speedup vs baseline: 1.2309x; 1.1695x over previous
#include <cuda_runtime.h>
#include <cuda_fp16.h>
#include <cstdint>

// ---------------------------------------------------------------------------
// FCOS head, fp16 mma.sync (m16n8k16, fp32 accum). Level-batched. Two streams
// (cls/reg). R15: K-chunk 64 (36 stages), 3-slot XOR-swizzled ring (32KB/slot),
// pad-free 128B rows. Otherwise identical to R14.
// ---------------------------------------------------------------------------

#define TP 20267
#define TOTE 10376704
#define NTILES 319
#define STAGE_BYTES 32768      // A 16KB + B 16KB
#define DYN_SMEM (3 * STAGE_BYTES)
#define WTN 2359296            // 4*9*256*256

__device__ __half g_xh[TOTE];
__device__ __half g_actA[TOTE];
__device__ __half g_actB[TOTE];
__device__ __half g_actC[TOTE];
__device__ __half g_actD[TOTE];
__device__ float  g_y[TOTE];
__device__ float  g_y2[TOTE];
__device__ float  g_gnsum[4 * 640];
__device__ float  g_gnsq[4 * 640];
__device__ float  g_scale[2 * 2560];
__device__ float  g_shift[2 * 2560];
__device__ float  g_regb[26];
__device__ __half g_wt_cls[WTN];                 // [s][tap][oc][ic]
__device__ __half g_wt_reg[WTN];
__device__ __half g_wtc_out[9 * 128 * 256];      // [tap][ocpad][ic]
__device__ __half g_wtr_out[9 * 128 * 256];

__constant__ int c_Hs[5] = {100, 50, 25, 13, 7};
__constant__ int c_Ws[5] = {152, 76, 38, 19, 10};
__constant__ int c_HWs[5] = {15200, 3800, 950, 247, 70};
__constant__ int c_Ps[5] = {30400, 7600, 1900, 494, 140};
__constant__ int c_tb[5] = {0, 238, 298, 313, 317};
__constant__ int c_ao[5] = {0, 7782400, 9728000, 10214400, 10340864};
__constant__ int c_lb[5] = {0, 15200, 19000, 19950, 20197};

__constant__ long long c_base[26] = {
    3242720LL, 3242720LL, 3242720LL, 3242720LL,
    3404856LL,
    3445390LL, 3445390LL, 3445390LL,
    3566992LL,
    3607526LL, 3607526LL, 3607526LL, 3607526LL, 3607526LL, 3607526LL,
    3607526LL, 3607526LL, 3607526LL, 3607526LL, 3607526LL, 3607526LL,
    3607526LL, 3607526LL, 3607526LL, 3607526LL,
    4256070LL};
__constant__ int c_ctot[26] = {4, 4, 4, 4, 1, 3, 3, 3, 1,
                               16, 16, 16, 16, 16, 16, 16, 16,
                               16, 16, 16, 16, 16, 16, 16, 16, 1};
__constant__ int c_ch[26] = {0, 1, 2, 3, 0, 0, 1, 2, 0,
                             0, 1, 2, 3, 4, 5, 6, 7,
                             8, 9, 10, 11, 12, 13, 14, 15, 0};
__constant__ int c_relu[26] = {1, 1, 1, 1, 0, 0, 0, 0, 0,
                               0, 0, 0, 0, 0, 0, 0, 0,
                               0, 0, 0, 0, 0, 0, 0, 0, 0};

__device__ __forceinline__ void cpa16p(uint32_t d, const void* s, int sz) {
    asm volatile("cp.async.cg.shared.global [%0], [%1], 16, %2;" ::"r"(d), "l"(s), "r"(sz));
}
#define LDSM4(r0, r1, r2, r3, a)                                           \
    asm volatile("ldmatrix.sync.aligned.m8n8.x4.shared.b16 {%0,%1,%2,%3}, [%4];" \
                 : "=r"(r0), "=r"(r1), "=r"(r2), "=r"(r3) : "r"(a))

// ---------------------------------------------------------------------------
__global__ void to_nhwc_half(const float* __restrict__ f0, const float* __restrict__ f1,
                             const float* __restrict__ f2, const float* __restrict__ f3,
                             const float* __restrict__ f4, __half* __restrict__ xh) {
    __shared__ float t[32][33];
    int z = blockIdx.z;
    int lvl = z >> 1, n = z & 1;
    int HW = c_HWs[lvl];
    int p0 = blockIdx.x * 32;
    if (p0 >= HW) return;
    const float* src = lvl == 0 ? f0 : lvl == 1 ? f1 : lvl == 2 ? f2 : lvl == 3 ? f3 : f4;
    __half* dst = xh + c_ao[lvl];
    int c0 = blockIdx.y * 32;
    int tx = threadIdx.x, ty = threadIdx.y;
    int p = p0 + tx;
    if (p < HW) t[ty][tx] = src[((size_t)(n * 256 + c0 + ty)) * HW + p];
    __syncthreads();
    int p2 = p0 + ty, c2 = c0 + tx;
    if (p2 < HW) dst[((size_t)(n * HW + p2)) * 256 + c2] = __float2half_rn(t[tx][ty]);
}

__global__ void pack_w_path(const float* __restrict__ w, __half* __restrict__ d) {
    int i = blockIdx.x * blockDim.x + threadIdx.x;
    if (i >= WTN) return;
    int ic = i & 255;
    int oc = (i >> 8) & 255;
    int tap = (i >> 16) % 9;
    int s = i / 589824;
    d[i] = __float2half_rn(w[(((size_t)(s * 256 + oc) * 256 + ic) * 9) + tap]);
}

__global__ void pack_small_cls(const float* __restrict__ cls_out_w) {
    int idx = blockIdx.x * blockDim.x + threadIdx.x;
    const int HN = 9 * 128 * 256;
    if (idx < HN) {
        int ic = idx & 255;
        int oc = (idx >> 8) & 127;
        int tap = idx >> 15;
        float v = (oc < 80) ? cls_out_w[((size_t)oc * 256 + ic) * 9 + tap] : 0.f;
        g_wtc_out[idx] = __float2half_rn(v);
    } else if (idx < HN + 2560) {
        g_gnsum[idx - HN] = 0.f;
    } else if (idx < HN + 5120) {
        g_gnsq[idx - HN - 2560] = 0.f;
    }
}

__global__ void pack_small_reg(
    const float* __restrict__ bbox_w, const float* __restrict__ bbox_b,
    const float* __restrict__ ctr_w,  const float* __restrict__ ctr_b,
    const float* __restrict__ dim_w,  const float* __restrict__ dim_b,
    const float* __restrict__ ori_w,  const float* __restrict__ ori_b,
    const float* __restrict__ kp_w,   const float* __restrict__ kp_b,
    const float* __restrict__ depth_w,const float* __restrict__ depth_b) {
    int idx = blockIdx.x * blockDim.x + threadIdx.x;
    const int HN = 9 * 128 * 256;
    if (idx < HN) {
        int ic = idx & 255;
        int oc = (idx >> 8) & 127;
        int tap = idx >> 15;
        float v = 0.f;
        if (oc < 26) {
            const float* src;
            if (oc < 4)       src = bbox_w + oc * 2304;
            else if (oc == 4) src = ctr_w;
            else if (oc < 8)  src = dim_w + (oc - 5) * 2304;
            else if (oc == 8) src = ori_w;
            else if (oc < 25) src = kp_w + (oc - 9) * 2304;
            else              src = depth_w;
            v = src[ic * 9 + tap];
        }
        g_wtr_out[idx] = __float2half_rn(v);
    } else if (idx < HN + 26) {
        int oc = idx - HN;
        float b;
        if (oc < 4)       b = bbox_b[oc];
        else if (oc == 4) b = ctr_b[0];
        else if (oc < 8)  b = dim_b[oc - 5];
        else if (oc == 8) b = ori_b[0];
        else if (oc < 25) b = kp_b[oc - 9];
        else              b = depth_b[0];
        g_regb[oc] = b;
    }
}

// ---------------------------------------------------------------------------
// Per-path fp16 implicit-GEMM conv. M=128 x N=128, 8 warps (64x32 each).
// K-chunk 64 (36 stages), 3-slot XOR-swizzled ring, 128B rows.
// kind 0: tower, grid (NTILES,2); kind 1: head, grid (NTILES,1).
// ---------------------------------------------------------------------------
__global__ __launch_bounds__(256, 2) void gemm16(
    const __half* __restrict__ xg, const __half* __restrict__ wt,
    const float* __restrict__ bias, float* __restrict__ outp,
    float* __restrict__ gsum, float* __restrict__ gsq, int kind, int path) {
    extern __shared__ __align__(16) uint32_t dynsm[];
    __shared__ int syy[128], sxx[128], sn[128];

    const int NST = 36;
    int tid = threadIdx.x;
    int bx = blockIdx.x, by = blockIdx.y;
    int lvl = (bx >= c_tb[1]) + (bx >= c_tb[2]) + (bx >= c_tb[3]) + (bx >= c_tb[4]);
    int H = c_Hs[lvl], W = c_Ws[lvl], HW = c_HWs[lvl], P = c_Ps[lvl];
    int p0 = (bx - c_tb[lvl]) * 128;

    int oc0, OC;
    if (kind == 0) { oc0 = by * 128; OC = 256; }
    else           { oc0 = 0; OC = path ? 26 : 80; }
    const __half* x = xg + c_ao[lvl];

    if (tid < 128) {
        int p = p0 + tid;
        if (p < P) {
            int n = p >= HW ? 1 : 0;
            int rr = p - n * HW;
            int yy = rr / W;
            syy[tid] = yy;
            sxx[tid] = rr - yy * W;
            sn[tid] = n;
        } else {
            syy[tid] = -100000;
            sxx[tid] = -100000;
            sn[tid] = 0;
        }
    }
    __syncthreads();

    int warp = tid >> 5, lane = tid & 31, g = lane >> 2, t4 = lane & 3;
    int mwarp = (warp >> 2) * 64, nwarp = (warp & 3) * 32;

    float acc[4][4][4];
#pragma unroll
    for (int i = 0; i < 4; i++)
#pragma unroll
        for (int j = 0; j < 4; j++)
#pragma unroll
            for (int q = 0; q < 4; q++) acc[i][j][q] = 0.f;

    // staging ownership: 8 threads per row, one 16B chunk each, 4 row-passes
    int m0 = tid >> 3, cw0 = tid & 7;
    uint32_t smbase = (uint32_t)__cvta_generic_to_shared(dynsm);

    // ldmatrix row bases (swizzled column computed per kb)
    int rA0 = mwarp + (lane & 15);
    int hiA = lane >> 4;
    int rB0 = nwarp + ((lane >> 4) << 3) + (lane & 7);
    int hiB = (lane >> 3) & 1;

    auto load_chunk = [&](int c, int slot) {
        int tap = c >> 2;
        int icc = (c & 3) << 6;
        int ty = tap / 3;
        int dy = ty - 1, dx = tap - ty * 3 - 1;
        uint32_t base = smbase + slot * STAGE_BYTES;
        uint32_t sw = (uint32_t)(cw0) << 4;
#pragma unroll
        for (int j = 0; j < 4; j++) {
            int m = m0 + j * 32;
            int gy = syy[m] + dy, gx = sxx[m] + dx;
            bool v = ((unsigned)gy < (unsigned)H) && ((unsigned)gx < (unsigned)W);
            const __half* src =
                x + ((size_t)(sn[m] * HW + gy * W + gx) * 256 + icc + cw0 * 8);
            cpa16p(base + m * 128 + (((uint32_t)(cw0 ^ (m & 7))) << 4),
                   v ? src : (const __half*)x, v ? 16 : 0);
        }
        const __half* wbase =
            kind ? wt + ((size_t)(tap * 128)) * 256
                 : wt + ((size_t)(tap * 256 + oc0)) * 256;
#pragma unroll
        for (int j = 0; j < 4; j++) {
            int r = m0 + j * 32;
            cpa16p(base + 16384 + r * 128 + (((uint32_t)(cw0 ^ (r & 7))) << 4),
                   wbase + (size_t)r * 256 + icc + cw0 * 8, 16);
        }
        asm volatile("cp.async.commit_group;");
        (void)sw;
    };

    load_chunk(0, 0);
    load_chunk(1, 1);

    for (int s = 0; s < NST; s++) {
        if (s + 1 < NST) {
            asm volatile("cp.async.wait_group 1;");
        } else {
            asm volatile("cp.async.wait_group 0;");
        }
        __syncthreads();
        if (s + 2 < NST) load_chunk(s + 2, (s + 2) % 3);

        uint32_t sb = smbase + (s % 3) * STAGE_BYTES;
#pragma unroll
        for (int kb = 0; kb < 4; kb++) {
            int ch = kb * 2;
            uint32_t A[4][4], Bv[2][4];
#pragma unroll
            for (int mt = 0; mt < 4; mt++) {
                int row = rA0 + mt * 16;
                LDSM4(A[mt][0], A[mt][1], A[mt][2], A[mt][3],
                      sb + row * 128 + ((uint32_t)((ch + hiA) ^ (row & 7)) << 4));
            }
#pragma unroll
            for (int ntp = 0; ntp < 2; ntp++) {
                int row = rB0 + ntp * 16;
                LDSM4(Bv[ntp][0], Bv[ntp][1], Bv[ntp][2], Bv[ntp][3],
                      sb + 16384 + row * 128 +
                          ((uint32_t)((ch + hiB) ^ (row & 7)) << 4));
            }
#pragma unroll
            for (int mt = 0; mt < 4; mt++)
#pragma unroll
                for (int nt = 0; nt < 4; nt++) {
                    int ntp = nt >> 1, j = nt & 1;
                    asm volatile(
                        "mma.sync.aligned.m16n8k16.row.col.f32.f16.f16.f32 "
                        "{%0,%1,%2,%3}, {%4,%5,%6,%7}, {%8,%9}, {%0,%1,%2,%3};"
                        : "+f"(acc[mt][nt][0]), "+f"(acc[mt][nt][1]),
                          "+f"(acc[mt][nt][2]), "+f"(acc[mt][nt][3])
                        : "r"(A[mt][0]), "r"(A[mt][1]), "r"(A[mt][2]), "r"(A[mt][3]),
                          "r"(Bv[ntp][j * 2]), "r"(Bv[ntp][j * 2 + 1]));
                }
        }
    }

    // epilogue
#pragma unroll
    for (int nt = 0; nt < 4; nt++) {
        int oc = oc0 + nwarp + nt * 8 + 2 * t4;
        float s0 = 0.f, q0 = 0.f, s1 = 0.f, q1 = 0.f;
#pragma unroll
        for (int mt = 0; mt < 4; mt++) {
#pragma unroll
            for (int hf = 0; hf < 2; hf++) {
                int r = mwarp + mt * 16 + g + hf * 8;
                if (p0 + r >= P) continue;
                float v0 = acc[mt][nt][hf * 2];
                float v1 = acc[mt][nt][hf * 2 + 1];
                if (kind == 0) {
                    v0 += __ldg(&bias[oc]);
                    v1 += __ldg(&bias[oc + 1]);
                    size_t ob = (size_t)c_ao[lvl] + (size_t)(p0 + r) * 256 + oc;
                    float2 st = {v0, v1};
                    *(float2*)&outp[ob] = st;
                    if (sn[r]) { s1 += v0 + v1; q1 += v0 * v0 + v1 * v1; }
                    else       { s0 += v0 + v1; q0 += v0 * v0 + v1 * v1; }
                } else if (oc < OC) {
                    long long unit =
                        (long long)sn[r] * TP + c_lb[lvl] + syy[r] * W + sxx[r];
                    v0 += __ldg(&bias[oc]);
                    v1 += __ldg(&bias[oc + 1]);
                    if (path == 0) {
                        outp[unit * 80 + oc] = v0;
                        outp[unit * 80 + oc + 1] = v1;
                    } else {
                        bool two = (oc + 1) < OC;
                        if (c_relu[oc]) v0 = fmaxf(v0, 0.f);
                        outp[c_base[oc] + unit * c_ctot[oc] + c_ch[oc]] = v0;
                        if (two) {
                            if (c_relu[oc + 1]) v1 = fmaxf(v1, 0.f);
                            outp[c_base[oc + 1] + unit * c_ctot[oc + 1] +
                                 c_ch[oc + 1]] = v1;
                        }
                    }
                }
            }
        }
        if (kind == 0) {
#pragma unroll
            for (int o = 16; o > 0; o >>= 1) {
                s0 += __shfl_xor_sync(0xffffffffu, s0, o);
                q0 += __shfl_xor_sync(0xffffffffu, q0, o);
                s1 += __shfl_xor_sync(0xffffffffu, s1, o);
                q1 += __shfl_xor_sync(0xffffffffu, q1, o);
            }
            if (lane == 0) {
                int gb = lvl * 64 + ((oc0 + nwarp + nt * 8) >> 3);
                atomicAdd(&gsum[gb], s0);
                atomicAdd(&gsq[gb], q0);
                if (s1 != 0.f || q1 != 0.f) {
                    atomicAdd(&gsum[gb + 32], s1);
                    atomicAdd(&gsq[gb + 32], q1);
                }
            }
        }
    }
}

// ---------------------------------------------------------------------------
__global__ void gn_coef(const float* __restrict__ gsum, const float* __restrict__ gsq,
                        const float* __restrict__ gam, const float* __restrict__ bet,
                        float* __restrict__ scl, float* __restrict__ shf) {
    int ng = blockIdx.x * blockDim.x + threadIdx.x;
    if (ng >= 320) return;
    int l = ng >> 6;
    int r = ng & 63;
    int n = r >> 5, gr = r & 31;
    float M = 8.f * c_HWs[l];
    float mu = gsum[ng] / M;
    float iv = rsqrtf(gsq[ng] / M - mu * mu + 1e-5f);
    int base = l * 512 + n * 256 + gr * 8;
#pragma unroll
    for (int j = 0; j < 8; j++) {
        int c = gr * 8 + j;
        float s = iv * gam[c];
        scl[base + j] = s;
        shf[base + j] = bet[c] - mu * s;
    }
}

__global__ void gn_apply(const float* __restrict__ y, __half* __restrict__ act,
                         const float* __restrict__ scl, const float* __restrict__ shf) {
    int idx = blockIdx.x * blockDim.x + threadIdx.x;
    if (idx >= TOTE / 4) return;
    int e = idx * 4;
    int l = (e >= c_ao[1]) + (e >= c_ao[2]) + (e >= c_ao[3]) + (e >= c_ao[4]);
    int c = e & 255;
    int pl = (e - c_ao[l]) >> 8;
    int n = pl >= c_HWs[l] ? 1 : 0;
    int cb = l * 512 + n * 256 + c;
    float4 sc = *(const float4*)&scl[cb];
    float4 sh = *(const float4*)&shf[cb];
    float4 v = *(const float4*)&y[e];
    __half2 h0 = __floats2half2_rn(fmaxf(v.x * sc.x + sh.x, 0.f),
                                   fmaxf(v.y * sc.y + sh.y, 0.f));
    __half2 h1 = __floats2half2_rn(fmaxf(v.z * sc.z + sh.z, 0.f),
                                   fmaxf(v.w * sc.w + sh.w, 0.f));
    uint2 st = {*(uint32_t*)&h0, *(uint32_t*)&h1};
    *(uint2*)&act[e] = st;
}

// ---------------------------------------------------------------------------
extern "C" void kernel_launch(void* const* d_in, const int* in_sizes, int n_in,
                              void* d_out, int out_size) {
    const float* feats[5];
    for (int i = 0; i < 5; i++) feats[i] = (const float*)d_in[i];
    const float* cls_conv_w = (const float*)d_in[5];
    const float* cls_conv_b = (const float*)d_in[6];
    const float* cls_gn_w = (const float*)d_in[7];
    const float* cls_gn_b = (const float*)d_in[8];
    const float* cls_out_w = (const float*)d_in[9];
    const float* cls_out_b = (const float*)d_in[10];
    const float* reg_conv_w = (const float*)d_in[11];
    const float* reg_conv_b = (const float*)d_in[12];
    const float* reg_gn_w = (const float*)d_in[13];
    const float* reg_gn_b = (const float*)d_in[14];
    float* out = (float*)d_out;

    __half *xh, *actA, *actB, *actC, *actD, *wtc, *wtr, *wtco, *wtro;
    float *ybuf, *ybuf2, *regb, *gsum, *gsq, *scl, *shf;
    cudaGetSymbolAddress((void**)&xh, g_xh);
    cudaGetSymbolAddress((void**)&actA, g_actA);
    cudaGetSymbolAddress((void**)&actB, g_actB);
    cudaGetSymbolAddress((void**)&actC, g_actC);
    cudaGetSymbolAddress((void**)&actD, g_actD);
    cudaGetSymbolAddress((void**)&ybuf, g_y);
    cudaGetSymbolAddress((void**)&ybuf2, g_y2);
    cudaGetSymbolAddress((void**)&regb, g_regb);
    cudaGetSymbolAddress((void**)&wtc, g_wt_cls);
    cudaGetSymbolAddress((void**)&wtr, g_wt_reg);
    cudaGetSymbolAddress((void**)&wtco, g_wtc_out);
    cudaGetSymbolAddress((void**)&wtro, g_wtr_out);
    cudaGetSymbolAddress((void**)&gsum, g_gnsum);
    cudaGetSymbolAddress((void**)&gsq, g_gnsq);
    cudaGetSymbolAddress((void**)&scl, g_scale);
    cudaGetSymbolAddress((void**)&shf, g_shift);

    cudaFuncSetAttribute(gemm16, cudaFuncAttributeMaxDynamicSharedMemorySize,
                         DYN_SMEM);

    static cudaStream_t s1 = nullptr;
    static cudaEvent_t eF = nullptr, eJ = nullptr;
    if (!s1) {
        cudaStreamCreateWithFlags(&s1, cudaStreamNonBlocking);
        cudaEventCreateWithFlags(&eF, cudaEventDisableTiming);
        cudaEventCreateWithFlags(&eJ, cudaEventDisableTiming);
    }

    // prologue: stream0 = cls packs + stat zeroing + transpose; s1 = reg packs
    pack_w_path<<<(WTN + 255) / 256, 256>>>(cls_conv_w, wtc);
    {
        int tot = 9 * 128 * 256 + 5120;
        pack_small_cls<<<(tot + 255) / 256, 256>>>(cls_out_w);
    }
    to_nhwc_half<<<dim3(475, 8, 10), dim3(32, 32)>>>(feats[0], feats[1], feats[2],
                                                     feats[3], feats[4], xh);
    cudaEventRecord(eF, 0);

    pack_w_path<<<(WTN + 255) / 256, 256, 0, s1>>>(reg_conv_w, wtr);
    {
        int tot = 9 * 128 * 256 + 26;
        pack_small_reg<<<(tot + 255) / 256, 256, 0, s1>>>(
            (const float*)d_in[15], (const float*)d_in[16],
            (const float*)d_in[17], (const float*)d_in[18],
            (const float*)d_in[19], (const float*)d_in[20],
            (const float*)d_in[21], (const float*)d_in[22],
            (const float*)d_in[23], (const float*)d_in[24],
            (const float*)d_in[25], (const float*)d_in[26]);
    }
    cudaStreamWaitEvent(s1, eF, 0);

    int gApplyX = (TOTE / 4 + 255) / 256;

    // --- cls chain (default stream) ---
    {
        const __half* cur = xh;
        __half* cd[4] = {actA, actB, actA, actB};
        for (int s = 0; s < 4; s++) {
            gemm16<<<dim3(NTILES, 2), 256, DYN_SMEM>>>(
                cur, wtc + (size_t)s * 589824, cls_conv_b + s * 256, ybuf,
                gsum + s * 640, gsq + s * 640, 0, 0);
            gn_coef<<<2, 160>>>(gsum + s * 640, gsq + s * 640,
                                cls_gn_w + s * 256, cls_gn_b + s * 256, scl, shf);
            gn_apply<<<gApplyX, 256>>>(ybuf, cd[s], scl, shf);
            cur = cd[s];
        }
        gemm16<<<dim3(NTILES, 1), 256, DYN_SMEM>>>(actB, wtco, cls_out_b, out,
                                                   nullptr, nullptr, 1, 0);
    }

    // --- reg chain (s1) ---
    {
        const __half* cur = xh;
        __half* rd[4] = {actC, actD, actC, actD};
        for (int s = 0; s < 4; s++) {
            gemm16<<<dim3(NTILES, 2), 256, DYN_SMEM, s1>>>(
                cur, wtr + (size_t)s * 589824, reg_conv_b + s * 256, ybuf2,
                gsum + s * 640 + 320, gsq + s * 640 + 320, 0, 1);
            gn_coef<<<2, 160, 0, s1>>>(gsum + s * 640 + 320, gsq + s * 640 + 320,
                                       reg_gn_w + s * 256, reg_gn_b + s * 256,
                                       scl + 2560, shf + 2560);
            gn_apply<<<gApplyX, 256, 0, s1>>>(ybuf2, rd[s], scl + 2560, shf + 2560);
            cur = rd[s];
        }
        gemm16<<<dim3(NTILES, 1), 256, DYN_SMEM, s1>>>(actD, wtro, regb, out,
                                                       nullptr, nullptr, 1, 1);
    }

    // join
    cudaEventRecord(eJ, s1);
    cudaStreamWaitEvent(0, eJ, 0);

    (void)in_sizes; (void)n_in; (void)out_size;
}

// round 17
// speedup vs baseline: 1.2365x; 1.0045x over previous
#include <cuda_runtime.h>
#include <cuda_fp16.h>
#include <cstdint>

// ---------------------------------------------------------------------------
// FCOS head, fp16 mma.sync (m16n8k16, fp32 accum). Level-batched. Two streams
// (cls/reg). R15 gemm core (K-chunk 64, 36 stages, 3-slot XOR ring).
// R16: gn_apply ILP x4; earlier stream fork (event right after transpose+zero).
// ---------------------------------------------------------------------------

#define TP 20267
#define TOTE 10376704
#define NTILES 319
#define STAGE_BYTES 32768      // A 16KB + B 16KB
#define DYN_SMEM (3 * STAGE_BYTES)
#define WTN 2359296            // 4*9*256*256
#define QF4 648544             // TOTE/16: float4s per ILP plane

__device__ __half g_xh[TOTE];
__device__ __half g_actA[TOTE];
__device__ __half g_actB[TOTE];
__device__ __half g_actC[TOTE];
__device__ __half g_actD[TOTE];
__device__ float  g_y[TOTE];
__device__ float  g_y2[TOTE];
__device__ float  g_gnsum[4 * 640];
__device__ float  g_gnsq[4 * 640];
__device__ float  g_scale[2 * 2560];
__device__ float  g_shift[2 * 2560];
__device__ float  g_regb[26];
__device__ __half g_wt_cls[WTN];                 // [s][tap][oc][ic]
__device__ __half g_wt_reg[WTN];
__device__ __half g_wtc_out[9 * 128 * 256];      // [tap][ocpad][ic]
__device__ __half g_wtr_out[9 * 128 * 256];

__constant__ int c_Hs[5] = {100, 50, 25, 13, 7};
__constant__ int c_Ws[5] = {152, 76, 38, 19, 10};
__constant__ int c_HWs[5] = {15200, 3800, 950, 247, 70};
__constant__ int c_Ps[5] = {30400, 7600, 1900, 494, 140};
__constant__ int c_tb[5] = {0, 238, 298, 313, 317};
__constant__ int c_ao[5] = {0, 7782400, 9728000, 10214400, 10340864};
__constant__ int c_lb[5] = {0, 15200, 19000, 19950, 20197};

__constant__ long long c_base[26] = {
    3242720LL, 3242720LL, 3242720LL, 3242720LL,
    3404856LL,
    3445390LL, 3445390LL, 3445390LL,
    3566992LL,
    3607526LL, 3607526LL, 3607526LL, 3607526LL, 3607526LL, 3607526LL,
    3607526LL, 3607526LL, 3607526LL, 3607526LL, 3607526LL, 3607526LL,
    3607526LL, 3607526LL, 3607526LL, 3607526LL,
    4256070LL};
__constant__ int c_ctot[26] = {4, 4, 4, 4, 1, 3, 3, 3, 1,
                               16, 16, 16, 16, 16, 16, 16, 16,
                               16, 16, 16, 16, 16, 16, 16, 16, 1};
__constant__ int c_ch[26] = {0, 1, 2, 3, 0, 0, 1, 2, 0,
                             0, 1, 2, 3, 4, 5, 6, 7,
                             8, 9, 10, 11, 12, 13, 14, 15, 0};
__constant__ int c_relu[26] = {1, 1, 1, 1, 0, 0, 0, 0, 0,
                               0, 0, 0, 0, 0, 0, 0, 0,
                               0, 0, 0, 0, 0, 0, 0, 0, 0};

__device__ __forceinline__ void cpa16p(uint32_t d, const void* s, int sz) {
    asm volatile("cp.async.cg.shared.global [%0], [%1], 16, %2;" ::"r"(d), "l"(s), "r"(sz));
}
#define LDSM4(r0, r1, r2, r3, a)                                           \
    asm volatile("ldmatrix.sync.aligned.m8n8.x4.shared.b16 {%0,%1,%2,%3}, [%4];" \
                 : "=r"(r0), "=r"(r1), "=r"(r2), "=r"(r3) : "r"(a))

// ---------------------------------------------------------------------------
__global__ void to_nhwc_half(const float* __restrict__ f0, const float* __restrict__ f1,
                             const float* __restrict__ f2, const float* __restrict__ f3,
                             const float* __restrict__ f4, __half* __restrict__ xh) {
    __shared__ float t[32][33];
    int z = blockIdx.z;
    int lvl = z >> 1, n = z & 1;
    int HW = c_HWs[lvl];
    int p0 = blockIdx.x * 32;
    if (p0 >= HW) return;
    const float* src = lvl == 0 ? f0 : lvl == 1 ? f1 : lvl == 2 ? f2 : lvl == 3 ? f3 : f4;
    __half* dst = xh + c_ao[lvl];
    int c0 = blockIdx.y * 32;
    int tx = threadIdx.x, ty = threadIdx.y;
    int p = p0 + tx;
    if (p < HW) t[ty][tx] = src[((size_t)(n * 256 + c0 + ty)) * HW + p];
    __syncthreads();
    int p2 = p0 + ty, c2 = c0 + tx;
    if (p2 < HW) dst[((size_t)(n * HW + p2)) * 256 + c2] = __float2half_rn(t[tx][ty]);
}

__global__ void pack_w_path(const float* __restrict__ w, __half* __restrict__ d) {
    int i = blockIdx.x * blockDim.x + threadIdx.x;
    if (i >= WTN) return;
    int ic = i & 255;
    int oc = (i >> 8) & 255;
    int tap = (i >> 16) % 9;
    int s = i / 589824;
    d[i] = __float2half_rn(w[(((size_t)(s * 256 + oc) * 256 + ic) * 9) + tap]);
}

// stat zeroing only (needed by both streams before any tower gemm)
__global__ void zero_stats() {
    int i = blockIdx.x * blockDim.x + threadIdx.x;
    if (i < 2560) g_gnsum[i] = 0.f;
    else if (i < 5120) g_gnsq[i - 2560] = 0.f;
}

__global__ void pack_small_cls(const float* __restrict__ cls_out_w) {
    int idx = blockIdx.x * blockDim.x + threadIdx.x;
    const int HN = 9 * 128 * 256;
    if (idx < HN) {
        int ic = idx & 255;
        int oc = (idx >> 8) & 127;
        int tap = idx >> 15;
        float v = (oc < 80) ? cls_out_w[((size_t)oc * 256 + ic) * 9 + tap] : 0.f;
        g_wtc_out[idx] = __float2half_rn(v);
    }
}

__global__ void pack_small_reg(
    const float* __restrict__ bbox_w, const float* __restrict__ bbox_b,
    const float* __restrict__ ctr_w,  const float* __restrict__ ctr_b,
    const float* __restrict__ dim_w,  const float* __restrict__ dim_b,
    const float* __restrict__ ori_w,  const float* __restrict__ ori_b,
    const float* __restrict__ kp_w,   const float* __restrict__ kp_b,
    const float* __restrict__ depth_w,const float* __restrict__ depth_b) {
    int idx = blockIdx.x * blockDim.x + threadIdx.x;
    const int HN = 9 * 128 * 256;
    if (idx < HN) {
        int ic = idx & 255;
        int oc = (idx >> 8) & 127;
        int tap = idx >> 15;
        float v = 0.f;
        if (oc < 26) {
            const float* src;
            if (oc < 4)       src = bbox_w + oc * 2304;
            else if (oc == 4) src = ctr_w;
            else if (oc < 8)  src = dim_w + (oc - 5) * 2304;
            else if (oc == 8) src = ori_w;
            else if (oc < 25) src = kp_w + (oc - 9) * 2304;
            else              src = depth_w;
            v = src[ic * 9 + tap];
        }
        g_wtr_out[idx] = __float2half_rn(v);
    } else if (idx < HN + 26) {
        int oc = idx - HN;
        float b;
        if (oc < 4)       b = bbox_b[oc];
        else if (oc == 4) b = ctr_b[0];
        else if (oc < 8)  b = dim_b[oc - 5];
        else if (oc == 8) b = ori_b[0];
        else if (oc < 25) b = kp_b[oc - 9];
        else              b = depth_b[0];
        g_regb[oc] = b;
    }
}

// ---------------------------------------------------------------------------
// Per-path fp16 implicit-GEMM conv. M=128 x N=128, 8 warps (64x32 each).
// K-chunk 64 (36 stages), 3-slot XOR-swizzled ring, 128B rows.
// kind 0: tower, grid (NTILES,2); kind 1: head, grid (NTILES,1).
// ---------------------------------------------------------------------------
__global__ __launch_bounds__(256, 2) void gemm16(
    const __half* __restrict__ xg, const __half* __restrict__ wt,
    const float* __restrict__ bias, float* __restrict__ outp,
    float* __restrict__ gsum, float* __restrict__ gsq, int kind, int path) {
    extern __shared__ __align__(16) uint32_t dynsm[];
    __shared__ int syy[128], sxx[128], sn[128];

    const int NST = 36;
    int tid = threadIdx.x;
    int bx = blockIdx.x, by = blockIdx.y;
    int lvl = (bx >= c_tb[1]) + (bx >= c_tb[2]) + (bx >= c_tb[3]) + (bx >= c_tb[4]);
    int H = c_Hs[lvl], W = c_Ws[lvl], HW = c_HWs[lvl], P = c_Ps[lvl];
    int p0 = (bx - c_tb[lvl]) * 128;

    int oc0, OC;
    if (kind == 0) { oc0 = by * 128; OC = 256; }
    else           { oc0 = 0; OC = path ? 26 : 80; }
    const __half* x = xg + c_ao[lvl];

    if (tid < 128) {
        int p = p0 + tid;
        if (p < P) {
            int n = p >= HW ? 1 : 0;
            int rr = p - n * HW;
            int yy = rr / W;
            syy[tid] = yy;
            sxx[tid] = rr - yy * W;
            sn[tid] = n;
        } else {
            syy[tid] = -100000;
            sxx[tid] = -100000;
            sn[tid] = 0;
        }
    }
    __syncthreads();

    int warp = tid >> 5, lane = tid & 31, g = lane >> 2, t4 = lane & 3;
    int mwarp = (warp >> 2) * 64, nwarp = (warp & 3) * 32;

    float acc[4][4][4];
#pragma unroll
    for (int i = 0; i < 4; i++)
#pragma unroll
        for (int j = 0; j < 4; j++)
#pragma unroll
            for (int q = 0; q < 4; q++) acc[i][j][q] = 0.f;

    int m0 = tid >> 3, cw0 = tid & 7;
    uint32_t smbase = (uint32_t)__cvta_generic_to_shared(dynsm);

    int rA0 = mwarp + (lane & 15);
    int hiA = lane >> 4;
    int rB0 = nwarp + ((lane >> 4) << 3) + (lane & 7);
    int hiB = (lane >> 3) & 1;

    auto load_chunk = [&](int c, int slot) {
        int tap = c >> 2;
        int icc = (c & 3) << 6;
        int ty = tap / 3;
        int dy = ty - 1, dx = tap - ty * 3 - 1;
        uint32_t base = smbase + slot * STAGE_BYTES;
#pragma unroll
        for (int j = 0; j < 4; j++) {
            int m = m0 + j * 32;
            int gy = syy[m] + dy, gx = sxx[m] + dx;
            bool v = ((unsigned)gy < (unsigned)H) && ((unsigned)gx < (unsigned)W);
            const __half* src =
                x + ((size_t)(sn[m] * HW + gy * W + gx) * 256 + icc + cw0 * 8);
            cpa16p(base + m * 128 + (((uint32_t)(cw0 ^ (m & 7))) << 4),
                   v ? src : (const __half*)x, v ? 16 : 0);
        }
        const __half* wbase =
            kind ? wt + ((size_t)(tap * 128)) * 256
                 : wt + ((size_t)(tap * 256 + oc0)) * 256;
#pragma unroll
        for (int j = 0; j < 4; j++) {
            int r = m0 + j * 32;
            cpa16p(base + 16384 + r * 128 + (((uint32_t)(cw0 ^ (r & 7))) << 4),
                   wbase + (size_t)r * 256 + icc + cw0 * 8, 16);
        }
        asm volatile("cp.async.commit_group;");
    };

    load_chunk(0, 0);
    load_chunk(1, 1);

    for (int s = 0; s < NST; s++) {
        if (s + 1 < NST) {
            asm volatile("cp.async.wait_group 1;");
        } else {
            asm volatile("cp.async.wait_group 0;");
        }
        __syncthreads();
        if (s + 2 < NST) load_chunk(s + 2, (s + 2) % 3);

        uint32_t sb = smbase + (s % 3) * STAGE_BYTES;
#pragma unroll
        for (int kb = 0; kb < 4; kb++) {
            int ch = kb * 2;
            uint32_t A[4][4], Bv[2][4];
#pragma unroll
            for (int mt = 0; mt < 4; mt++) {
                int row = rA0 + mt * 16;
                LDSM4(A[mt][0], A[mt][1], A[mt][2], A[mt][3],
                      sb + row * 128 + ((uint32_t)((ch + hiA) ^ (row & 7)) << 4));
            }
#pragma unroll
            for (int ntp = 0; ntp < 2; ntp++) {
                int row = rB0 + ntp * 16;
                LDSM4(Bv[ntp][0], Bv[ntp][1], Bv[ntp][2], Bv[ntp][3],
                      sb + 16384 + row * 128 +
                          ((uint32_t)((ch + hiB) ^ (row & 7)) << 4));
            }
#pragma unroll
            for (int mt = 0; mt < 4; mt++)
#pragma unroll
                for (int nt = 0; nt < 4; nt++) {
                    int ntp = nt >> 1, j = nt & 1;
                    asm volatile(
                        "mma.sync.aligned.m16n8k16.row.col.f32.f16.f16.f32 "
                        "{%0,%1,%2,%3}, {%4,%5,%6,%7}, {%8,%9}, {%0,%1,%2,%3};"
                        : "+f"(acc[mt][nt][0]), "+f"(acc[mt][nt][1]),
                          "+f"(acc[mt][nt][2]), "+f"(acc[mt][nt][3])
                        : "r"(A[mt][0]), "r"(A[mt][1]), "r"(A[mt][2]), "r"(A[mt][3]),
                          "r"(Bv[ntp][j * 2]), "r"(Bv[ntp][j * 2 + 1]));
                }
        }
    }

    // epilogue
#pragma unroll
    for (int nt = 0; nt < 4; nt++) {
        int oc = oc0 + nwarp + nt * 8 + 2 * t4;
        float s0 = 0.f, q0 = 0.f, s1 = 0.f, q1 = 0.f;
#pragma unroll
        for (int mt = 0; mt < 4; mt++) {
#pragma unroll
            for (int hf = 0; hf < 2; hf++) {
                int r = mwarp + mt * 16 + g + hf * 8;
                if (p0 + r >= P) continue;
                float v0 = acc[mt][nt][hf * 2];
                float v1 = acc[mt][nt][hf * 2 + 1];
                if (kind == 0) {
                    v0 += __ldg(&bias[oc]);
                    v1 += __ldg(&bias[oc + 1]);
                    size_t ob = (size_t)c_ao[lvl] + (size_t)(p0 + r) * 256 + oc;
                    float2 st = {v0, v1};
                    *(float2*)&outp[ob] = st;
                    if (sn[r]) { s1 += v0 + v1; q1 += v0 * v0 + v1 * v1; }
                    else       { s0 += v0 + v1; q0 += v0 * v0 + v1 * v1; }
                } else if (oc < OC) {
                    long long unit =
                        (long long)sn[r] * TP + c_lb[lvl] + syy[r] * W + sxx[r];
                    v0 += __ldg(&bias[oc]);
                    v1 += __ldg(&bias[oc + 1]);
                    if (path == 0) {
                        outp[unit * 80 + oc] = v0;
                        outp[unit * 80 + oc + 1] = v1;
                    } else {
                        bool two = (oc + 1) < OC;
                        if (c_relu[oc]) v0 = fmaxf(v0, 0.f);
                        outp[c_base[oc] + unit * c_ctot[oc] + c_ch[oc]] = v0;
                        if (two) {
                            if (c_relu[oc + 1]) v1 = fmaxf(v1, 0.f);
                            outp[c_base[oc + 1] + unit * c_ctot[oc + 1] +
                                 c_ch[oc + 1]] = v1;
                        }
                    }
                }
            }
        }
        if (kind == 0) {
#pragma unroll
            for (int o = 16; o > 0; o >>= 1) {
                s0 += __shfl_xor_sync(0xffffffffu, s0, o);
                q0 += __shfl_xor_sync(0xffffffffu, q0, o);
                s1 += __shfl_xor_sync(0xffffffffu, s1, o);
                q1 += __shfl_xor_sync(0xffffffffu, q1, o);
            }
            if (lane == 0) {
                int gb = lvl * 64 + ((oc0 + nwarp + nt * 8) >> 3);
                atomicAdd(&gsum[gb], s0);
                atomicAdd(&gsq[gb], q0);
                if (s1 != 0.f || q1 != 0.f) {
                    atomicAdd(&gsum[gb + 32], s1);
                    atomicAdd(&gsq[gb + 32], q1);
                }
            }
        }
    }
}

// ---------------------------------------------------------------------------
__global__ void gn_coef(const float* __restrict__ gsum, const float* __restrict__ gsq,
                        const float* __restrict__ gam, const float* __restrict__ bet,
                        float* __restrict__ scl, float* __restrict__ shf) {
    int ng = blockIdx.x * blockDim.x + threadIdx.x;
    if (ng >= 320) return;
    int l = ng >> 6;
    int r = ng & 63;
    int n = r >> 5, gr = r & 31;
    float M = 8.f * c_HWs[l];
    float mu = gsum[ng] / M;
    float iv = rsqrtf(gsq[ng] / M - mu * mu + 1e-5f);
    int base = l * 512 + n * 256 + gr * 8;
#pragma unroll
    for (int j = 0; j < 8; j++) {
        int c = gr * 8 + j;
        float s = iv * gam[c];
        scl[base + j] = s;
        shf[base + j] = bet[c] - mu * s;
    }
}

// gn_apply, ILP x4: each thread handles 4 strided float4 quads.
__global__ void gn_apply(const float* __restrict__ y, __half* __restrict__ act,
                         const float* __restrict__ scl, const float* __restrict__ shf) {
    int idx = blockIdx.x * blockDim.x + threadIdx.x;
    if (idx >= QF4) return;
#pragma unroll
    for (int q = 0; q < 4; q++) {
        int f4 = idx + q * QF4;
        int e = f4 * 4;
        int l = (e >= c_ao[1]) + (e >= c_ao[2]) + (e >= c_ao[3]) + (e >= c_ao[4]);
        int c = e & 255;
        int pl = (e - c_ao[l]) >> 8;
        int n = pl >= c_HWs[l] ? 1 : 0;
        int cb = l * 512 + n * 256 + c;
        float4 sc = *(const float4*)&scl[cb];
        float4 sh = *(const float4*)&shf[cb];
        float4 v = *(const float4*)&y[e];
        __half2 h0 = __floats2half2_rn(fmaxf(v.x * sc.x + sh.x, 0.f),
                                       fmaxf(v.y * sc.y + sh.y, 0.f));
        __half2 h1 = __floats2half2_rn(fmaxf(v.z * sc.z + sh.z, 0.f),
                                       fmaxf(v.w * sc.w + sh.w, 0.f));
        uint2 st = {*(uint32_t*)&h0, *(uint32_t*)&h1};
        *(uint2*)&act[e] = st;
    }
}

// ---------------------------------------------------------------------------
extern "C" void kernel_launch(void* const* d_in, const int* in_sizes, int n_in,
                              void* d_out, int out_size) {
    const float* feats[5];
    for (int i = 0; i < 5; i++) feats[i] = (const float*)d_in[i];
    const float* cls_conv_w = (const float*)d_in[5];
    const float* cls_conv_b = (const float*)d_in[6];
    const float* cls_gn_w = (const float*)d_in[7];
    const float* cls_gn_b = (const float*)d_in[8];
    const float* cls_out_w = (const float*)d_in[9];
    const float* cls_out_b = (const float*)d_in[10];
    const float* reg_conv_w = (const float*)d_in[11];
    const float* reg_conv_b = (const float*)d_in[12];
    const float* reg_gn_w = (const float*)d_in[13];
    const float* reg_gn_b = (const float*)d_in[14];
    float* out = (float*)d_out;

    __half *xh, *actA, *actB, *actC, *actD, *wtc, *wtr, *wtco, *wtro;
    float *ybuf, *ybuf2, *regb, *gsum, *gsq, *scl, *shf;
    cudaGetSymbolAddress((void**)&xh, g_xh);
    cudaGetSymbolAddress((void**)&actA, g_actA);
    cudaGetSymbolAddress((void**)&actB, g_actB);
    cudaGetSymbolAddress((void**)&actC, g_actC);
    cudaGetSymbolAddress((void**)&actD, g_actD);
    cudaGetSymbolAddress((void**)&ybuf, g_y);
    cudaGetSymbolAddress((void**)&ybuf2, g_y2);
    cudaGetSymbolAddress((void**)&regb, g_regb);
    cudaGetSymbolAddress((void**)&wtc, g_wt_cls);
    cudaGetSymbolAddress((void**)&wtr, g_wt_reg);
    cudaGetSymbolAddress((void**)&wtco, g_wtc_out);
    cudaGetSymbolAddress((void**)&wtro, g_wtr_out);
    cudaGetSymbolAddress((void**)&gsum, g_gnsum);
    cudaGetSymbolAddress((void**)&gsq, g_gnsq);
    cudaGetSymbolAddress((void**)&scl, g_scale);
    cudaGetSymbolAddress((void**)&shf, g_shift);

    cudaFuncSetAttribute(gemm16, cudaFuncAttributeMaxDynamicSharedMemorySize,
                         DYN_SMEM);

    static cudaStream_t s1 = nullptr;
    static cudaEvent_t eF = nullptr, eJ = nullptr;
    if (!s1) {
        cudaStreamCreateWithFlags(&s1, cudaStreamNonBlocking);
        cudaEventCreateWithFlags(&eF, cudaEventDisableTiming);
        cudaEventCreateWithFlags(&eJ, cudaEventDisableTiming);
    }

    // prologue stream0: transpose + stat zeroing FIRST, fork event, then cls packs
    to_nhwc_half<<<dim3(475, 8, 10), dim3(32, 32)>>>(feats[0], feats[1], feats[2],
                                                     feats[3], feats[4], xh);
    zero_stats<<<20, 256>>>();
    cudaEventRecord(eF, 0);
    pack_w_path<<<(WTN + 255) / 256, 256>>>(cls_conv_w, wtc);
    pack_small_cls<<<(9 * 128 * 256 + 255) / 256, 256>>>(cls_out_w);

    // prologue s1: reg packs (independent), then gate on transpose+zeroing
    pack_w_path<<<(WTN + 255) / 256, 256, 0, s1>>>(reg_conv_w, wtr);
    {
        int tot = 9 * 128 * 256 + 26;
        pack_small_reg<<<(tot + 255) / 256, 256, 0, s1>>>(
            (const float*)d_in[15], (const float*)d_in[16],
            (const float*)d_in[17], (const float*)d_in[18],
            (const float*)d_in[19], (const float*)d_in[20],
            (const float*)d_in[21], (const float*)d_in[22],
            (const float*)d_in[23], (const float*)d_in[24],
            (const float*)d_in[25], (const float*)d_in[26]);
    }
    cudaStreamWaitEvent(s1, eF, 0);

    int gApplyX = (QF4 + 255) / 256;

    // --- cls chain (default stream) ---
    {
        const __half* cur = xh;
        __half* cd[4] = {actA, actB, actA, actB};
        for (int s = 0; s < 4; s++) {
            gemm16<<<dim3(NTILES, 2), 256, DYN_SMEM>>>(
                cur, wtc + (size_t)s * 589824, cls_conv_b + s * 256, ybuf,
                gsum + s * 640, gsq + s * 640, 0, 0);
            gn_coef<<<2, 160>>>(gsum + s * 640, gsq + s * 640,
                                cls_gn_w + s * 256, cls_gn_b + s * 256, scl, shf);
            gn_apply<<<gApplyX, 256>>>(ybuf, cd[s], scl, shf);
            cur = cd[s];
        }
        gemm16<<<dim3(NTILES, 1), 256, DYN_SMEM>>>(actB, wtco, cls_out_b, out,
                                                   nullptr, nullptr, 1, 0);
    }

    // --- reg chain (s1) ---
    {
        const __half* cur = xh;
        __half* rd[4] = {actC, actD, actC, actD};
        for (int s = 0; s < 4; s++) {
            gemm16<<<dim3(NTILES, 2), 256, DYN_SMEM, s1>>>(
                cur, wtr + (size_t)s * 589824, reg_conv_b + s * 256, ybuf2,
                gsum + s * 640 + 320, gsq + s * 640 + 320, 0, 1);
            gn_coef<<<2, 160, 0, s1>>>(gsum + s * 640 + 320, gsq + s * 640 + 320,
                                       reg_gn_w + s * 256, reg_gn_b + s * 256,
                                       scl + 2560, shf + 2560);
            gn_apply<<<gApplyX, 256, 0, s1>>>(ybuf2, rd[s], scl + 2560, shf + 2560);
            cur = rd[s];
        }
        gemm16<<<dim3(NTILES, 1), 256, DYN_SMEM, s1>>>(actD, wtro, regb, out,
                                                       nullptr, nullptr, 1, 1);
    }

    // join
    cudaEventRecord(eJ, s1);
    cudaStreamWaitEvent(0, eJ, 0);

    (void)in_sizes; (void)n_in; (void)out_size;
}